// round 13
// baseline (speedup 1.0000x reference)
#include <cuda_runtime.h>
#include <cstdint>

// Problem constants
static constexpr int B_   = 4;
static constexpr int W_   = 12;
static constexpr int N_   = 1024;
static constexpr int FIN_ = 32;
static constexpr int FOUT_= 32;
static constexpr int H_   = 256;
static constexpr int BW_  = B_ * W_;        // 48
static constexpr int D_   = N_ * FOUT_;     // 32768
static constexpr int KC_  = 64;             // split-K chunks for gates GEMM (k=512 each)
static constexpr int KQ_  = 8;              // split-K for gcn GEMM (k=128 each)

// ---------------- packed f32x2 helpers ----------------
#define FMA2(acc, a, b) asm("fma.rn.f32x2 %0, %1, %2, %0;" : "+l"(acc) : "l"(a), "l"(b))
#define PACK2(d, f)     asm("mov.b64 %0, {%1, %1};" : "=l"(d) : "f"(f))
#define PACKPAIR(d, lo, hi) asm("mov.b64 %0, {%1, %2};" : "=l"(d) : "f"(lo), "f"(hi))
#define UNPACK2(lo, hi, d) asm("mov.b64 {%0, %1}, %2;" : "=f"(lo), "=f"(hi) : "l"(d))

// ---------------- cp.async helpers ----------------
__device__ __forceinline__ void cp16(uint32_t dst, const void* src) {
    asm volatile("cp.async.cg.shared.global [%0], [%1], 16;" :: "r"(dst), "l"(src));
}
#define CP_COMMIT() asm volatile("cp.async.commit_group;")
#define CP_WAIT1()  asm volatile("cp.async.wait_group 1;")
#define CP_WAIT0()  asm volatile("cp.async.wait_group 0;")

// ---------------- scratch (static device globals; no allocation) ----------------
__device__ float g_deg[BW_ * N_];
__device__ float g_P[(size_t)BW_ * N_ * FOUT_];
__device__ float g_xpart[(size_t)KQ_ * BW_ * N_ * FOUT_];   // gcn split-K partials
__device__ float g_XT[(size_t)D_ * BW_];                    // X transposed: [k][wb]
__device__ float g_part[(size_t)KC_ * BW_ * 4 * H_];        // gates split-K partials
__device__ float g_gates[BW_ * 4 * H_];
__device__ float g_whhT[(size_t)H_ * 4 * H_];               // [k][j*4+r] interleaved
__device__ float g_hn[B_ * H_];
__device__ float g_out[B_ * D_];
__device__ float g_s1[B_ * N_];
__device__ float g_s2[B_ * N_];

// ---------------- K0: transpose w_hh [4H][H] -> whhT [k][j*4+r] -----------------
// grid (32, 8), block (32, 8)
__global__ void k_whhT(const float* __restrict__ w_hh) {
    __shared__ float tile[32][33];
    int gb = blockIdx.x * 32;   // gate-row base (0..1023), never crosses 256 bnd
    int kb = blockIdx.y * 32;   // k base (0..255)
    int tx = threadIdx.x, ty = threadIdx.y;
#pragma unroll
    for (int i = 0; i < 32; i += 8)
        tile[ty + i][tx] = w_hh[(size_t)(gb + ty + i) * H_ + kb + tx];
    __syncthreads();
    int r = gb >> 8;            // gate index (0..3), same for all tx
    int jb = gb & 255;          // unit base
#pragma unroll
    for (int i = 0; i < 32; i += 8)
        g_whhT[(size_t)(kb + ty + i) * (4 * H_) + (jb + tx) * 4 + r] = tile[tx][ty + i];
}

// ---------------- K1: fused degree + P -------------------------------------------
__global__ void k_degP(const float* __restrict__ shots, const float* __restrict__ node,
                       const float* __restrict__ gcn_w) {
    __shared__ float gw[FIN_ * FOUT_];
    int r0 = blockIdx.x * 8;
    int w  = (r0 / N_) % W_;            // rows bw-major: bw = b*W + w
    for (int i = threadIdx.x; i < FIN_ * FOUT_; i += 256)
        gw[i] = gcn_w[(size_t)w * FIN_ * FOUT_ + i];
    __syncthreads();
    int warp = threadIdx.x >> 5, lane = threadIdx.x & 31;
    int r = r0 + warp;
    const float4* p = (const float4*)(shots + (size_t)r * N_);
    float s = 0.f;
#pragma unroll
    for (int i = 0; i < 8; i++) {
        float4 v = p[lane + 32 * i];
        s += v.x + v.y + v.z + v.w;
    }
#pragma unroll
    for (int o = 16; o; o >>= 1) s += __shfl_xor_sync(0xffffffffu, s, o);
    float d = 1.0f / sqrtf(1.0f + s);
    if (lane == 0) g_deg[r] = d;

    float nv = node[(size_t)r * FIN_ + lane];
    float acc = 0.f;
#pragma unroll
    for (int f = 0; f < FIN_; f++) {
        float x = __shfl_sync(0xffffffffu, nv, f);
        acc += x * gw[f * FOUT_ + lane];
    }
    g_P[(size_t)r * FOUT_ + lane] = d * acc;
}

// ---------------- K3: xpart[kq] = shots[n, kq-chunk] @ P[kq-chunk, :] ----------
static constexpr int AS_ = 292;   // A_shT row stride (floats)
__global__ __launch_bounds__(64) void k_gcn(const float* __restrict__ shots) {
    __shared__ __align__(16) float AT[16 * AS_];   // [kk][f(row)]
    __shared__ __align__(16) float PS[16 * 32];    // [kk][col]
    int bw = blockIdx.x >> 3;
    int n0 = (blockIdx.x & 7) << 7;      // * 128
    int kq = blockIdx.y;
    int t = threadIdx.x;
    int tx = t & 3;
    int ty = t >> 2;
    const float* Abase = shots + (size_t)bw * N_ * N_;
    const float* Pbase = g_P + (size_t)bw * N_ * FOUT_;

    unsigned long long acc[4][8];
#pragma unroll
    for (int i = 0; i < 4; i++)
#pragma unroll
        for (int j = 0; j < 8; j++) acc[i][j] = 0ull;

    const int r8 = ty * 8;
    const int fr = r8 + ((r8 >> 5) << 2);

    for (int k0 = kq * 128; k0 < kq * 128 + 128; k0 += 16) {
#pragma unroll
        for (int i = 0; i < 8; i++) {
            int idx = t + 64 * i;
            int rr = idx >> 2, q = idx & 3;
            float4 v = *(const float4*)(Abase + (size_t)(n0 + rr) * N_ + k0 + 4 * q);
            int f = rr + ((rr >> 5) << 2);
            AT[(4 * q + 0) * AS_ + f] = v.x;
            AT[(4 * q + 1) * AS_ + f] = v.y;
            AT[(4 * q + 2) * AS_ + f] = v.z;
            AT[(4 * q + 3) * AS_ + f] = v.w;
        }
#pragma unroll
        for (int i = 0; i < 2; i++) {
            int idx = t + 64 * i;
            int kk = idx >> 3, c = idx & 7;
            *(float4*)&PS[kk * 32 + 4 * c] =
                *(const float4*)(Pbase + (size_t)(k0 + kk) * 32 + 4 * c);
        }
        __syncthreads();
#pragma unroll 4
        for (int kk = 0; kk < 16; kk++) {
            ulonglong2 aA = *(const ulonglong2*)&AT[kk * AS_ + fr];
            ulonglong2 aB = *(const ulonglong2*)&AT[kk * AS_ + fr + 4];
            float4 p0 = *(const float4*)&PS[kk * 32 + tx * 8];
            float4 p1 = *(const float4*)&PS[kk * 32 + tx * 8 + 4];
            unsigned long long ap[4];
            ap[0] = aA.x; ap[1] = aA.y; ap[2] = aB.x; ap[3] = aB.y;
            unsigned long long bb[8];
            PACK2(bb[0], p0.x); PACK2(bb[1], p0.y); PACK2(bb[2], p0.z); PACK2(bb[3], p0.w);
            PACK2(bb[4], p1.x); PACK2(bb[5], p1.y); PACK2(bb[6], p1.z); PACK2(bb[7], p1.w);
#pragma unroll
            for (int i = 0; i < 4; i++)
#pragma unroll
                for (int j = 0; j < 8; j++) FMA2(acc[i][j], ap[i], bb[j]);
        }
        __syncthreads();
    }

    float* Xp = g_xpart + (size_t)kq * BW_ * N_ * FOUT_ + (size_t)bw * N_ * FOUT_;
#pragma unroll
    for (int i = 0; i < 4; i++) {
        int ne = n0 + r8 + 2 * i;
        float lo[8], hi[8];
#pragma unroll
        for (int j = 0; j < 8; j++) UNPACK2(lo[j], hi[j], acc[i][j]);
        float4 o0 = {lo[0], lo[1], lo[2], lo[3]};
        float4 o1 = {lo[4], lo[5], lo[6], lo[7]};
        float4 o2 = {hi[0], hi[1], hi[2], hi[3]};
        float4 o3 = {hi[4], hi[5], hi[6], hi[7]};
        *(float4*)(Xp + (size_t)ne * 32 + tx * 8) = o0;
        *(float4*)(Xp + (size_t)ne * 32 + tx * 8 + 4) = o1;
        *(float4*)(Xp + (size_t)(ne + 1) * 32 + tx * 8) = o2;
        *(float4*)(Xp + (size_t)(ne + 1) * 32 + tx * 8 + 4) = o3;
    }
}

// ---------------- K3f: XT[k][wb] = d[n]*(sum_kq xpart + P), smem-tiled transpose -
// 512 blocks x 256 thr; block handles 64 consecutive k-rows.
__global__ void k_xfin(void) {
    __shared__ float tile[64 * 49];    // [rr][wb'] (stride 49: conflict-free)
    int rt = blockIdx.x * 64;
    int t = threadIdx.x;
#pragma unroll 4
    for (int pass = 0; pass < 12; pass++) {
        int p = pass * 256 + t;
        int bw = p >> 6, rr = p & 63;
        int r = rt + rr;
        float s = g_P[(size_t)bw * D_ + r];
#pragma unroll
        for (int kq = 0; kq < KQ_; kq++)
            s += g_xpart[(size_t)kq * BW_ * D_ + (size_t)bw * D_ + r];
        s *= g_deg[bw * N_ + (r >> 5)];
        int w = bw % W_, b = bw / W_;
        tile[rr * 49 + (w * B_ + b)] = s;
    }
    __syncthreads();
#pragma unroll 4
    for (int pass = 0; pass < 12; pass++) {
        int o = pass * 256 + t;
        int rr = o / 48, c = o % 48;
        g_XT[(size_t)(rt + rr) * BW_ + c] = tile[rr * 49 + c];
    }
}

// ---------------- K4: gates_x = X @ w_ih^T  (dual cp.async, 4 blocks/SM) --------
static constexpr int WROW_ = 36;                  // W smem row stride (floats)
static constexpr int WBUF_ = 128 * WROW_;         // 4608 floats per buffer
static constexpr int XS_   = 52;                  // XT smem row stride
static constexpr int XBUF_ = 32 * XS_;            // 1664 floats per buffer
static constexpr int GATES_SMEM = (2 * WBUF_ + 2 * XBUF_) * 4;   // 50176 B

__global__ __launch_bounds__(192, 4) void k_gates(const float* __restrict__ w_ih) {
    extern __shared__ __align__(16) float sm[];
    float* WS = sm;                 // [2][128][36]
    float* XT = sm + 2 * WBUF_;     // [2][32][52]
    const int g0 = blockIdx.x * 128;
    const int kc = blockIdx.y;
    const int kbase = kc * 512;
    const int t = threadIdx.x;
    const int warp = t >> 5, gl = t & 31;
    const int wb0 = warp * 8;
    const uint32_t ws_smem = (uint32_t)__cvta_generic_to_shared(WS);
    const uint32_t xt_smem = (uint32_t)__cvta_generic_to_shared(XT);

    unsigned long long acc[4][4];
#pragma unroll
    for (int i = 0; i < 4; i++)
#pragma unroll
        for (int j = 0; j < 4; j++) acc[i][j] = 0ull;

#define STAGE(bufi, k0)                                                            \
    do {                                                                           \
        for (int idx = t; idx < 1024; idx += 192) {                                \
            int g = idx >> 3, q = idx & 7;                                         \
            cp16(ws_smem + ((bufi) * WBUF_ + g * WROW_ + 4 * q) * 4,               \
                 w_ih + (size_t)(g0 + g) * D_ + (k0) + 4 * q);                     \
        }                                                                          \
        for (int idx = t; idx < 384; idx += 192) {                                 \
            int kk = idx / 12, q = idx % 12;                                       \
            cp16(xt_smem + ((bufi) * XBUF_ + kk * XS_ + 4 * q) * 4,                \
                 g_XT + (size_t)((k0) + kk) * BW_ + 4 * q);                        \
        }                                                                          \
        CP_COMMIT();                                                               \
    } while (0)

    STAGE(0, kbase);

    for (int s = 0; s < 16; s++) {
        int buf = s & 1;
        __syncthreads();   // previous compute done -> other buffer free
        if (s < 15) {
            STAGE(buf ^ 1, kbase + 32 * (s + 1));
            CP_WAIT1();
        } else {
            CP_WAIT0();
        }
        __syncthreads();
        const float* WB = WS + buf * WBUF_;
        const float* XB = XT + buf * XBUF_;
#pragma unroll
        for (int kkc = 0; kkc < 8; kkc++) {
            unsigned long long ap[4][4];
#pragma unroll
            for (int kk = 0; kk < 4; kk++) {
                int krow = kkc * 4 + kk;
                ulonglong2 xA = *(const ulonglong2*)&XB[krow * XS_ + wb0];
                ulonglong2 xB2 = *(const ulonglong2*)&XB[krow * XS_ + wb0 + 4];
                ap[kk][0] = xA.x; ap[kk][1] = xA.y; ap[kk][2] = xB2.x; ap[kk][3] = xB2.y;
            }
#pragma unroll
            for (int j = 0; j < 4; j++) {
                float4 v = *(const float4*)&WB[(gl + 32 * j) * WROW_ + kkc * 4];
                float wf[4] = {v.x, v.y, v.z, v.w};
#pragma unroll
                for (int kk = 0; kk < 4; kk++) {
                    unsigned long long b2;
                    PACK2(b2, wf[kk]);
#pragma unroll
                    for (int i = 0; i < 4; i++) FMA2(acc[i][j], ap[kk][i], b2);
                }
            }
        }
    }
#undef STAGE

    // epilogue -> split-K partials
#pragma unroll
    for (int i = 0; i < 4; i++) {
#pragma unroll
        for (int j = 0; j < 4; j++) {
            float lo, hi;
            UNPACK2(lo, hi, acc[i][j]);
            int gcol = g0 + gl + 32 * j;
            g_part[((size_t)kc * BW_ + wb0 + 2 * i) * 1024 + gcol] = lo;
            g_part[((size_t)kc * BW_ + wb0 + 2 * i + 1) * 1024 + gcol] = hi;
        }
    }
}

// ---------------- K4r: reduce split-K + biases ----------------------------------
__global__ void k_greduce(const float* __restrict__ b_ih, const float* __restrict__ b_hh) {
    int i = blockIdx.x * 256 + threadIdx.x;   // 0..49151
    int g = i & 1023;
    float s = b_ih[g] + b_hh[g];
#pragma unroll 8
    for (int kc = 0; kc < KC_; kc++) s += g_part[(size_t)kc * BW_ * 1024 + i];
    g_gates[i] = s;
}

// ---------------- K5: fused 12-step LSTM (ONE block, all 4 batches, FMA2) -------
// 256 threads; thread j handles hidden unit j for ALL batches (weights read once).
// whhT interleaved: w4[k*H+j] = 4 gate weights (i,f,g,o) for unit j, input k.
// h stored [k][batch] float4 in smem -> broadcast LDS.128.
__global__ __launch_bounds__(256) void k_lstm() {
    __shared__ __align__(16) float hsh[2][H_][4];   // 8 KB
    int j = threadIdx.x;
    float cc[4] = {0.f, 0.f, 0.f, 0.f};
    *(float4*)&hsh[0][j][0] = make_float4(0.f, 0.f, 0.f, 0.f);
    __syncthreads();
    const float4* w4 = (const float4*)g_whhT;

    for (int w = 0; w < W_; w++) {
        int p = w & 1;
        // init accumulators (batch pairs packed: a01 = {b0,b1}, a23 = {b2,b3})
        unsigned long long a01[4], a23[4];
#pragma unroll
        for (int r = 0; r < 4; r++) {
            float v0 = g_gates[((size_t)(w * B_ + 0)) * 4 * H_ + r * H_ + j];
            float v1 = g_gates[((size_t)(w * B_ + 1)) * 4 * H_ + r * H_ + j];
            float v2 = g_gates[((size_t)(w * B_ + 2)) * 4 * H_ + r * H_ + j];
            float v3 = g_gates[((size_t)(w * B_ + 3)) * 4 * H_ + r * H_ + j];
            PACKPAIR(a01[r], v0, v1);
            PACKPAIR(a23[r], v2, v3);
        }
#pragma unroll 8
        for (int k = 0; k < H_; k++) {
            float4 hv = *(const float4*)&hsh[p][k][0];   // broadcast
            unsigned long long h01, h23;
            PACKPAIR(h01, hv.x, hv.y);
            PACKPAIR(h23, hv.z, hv.w);
            float4 wv = w4[(size_t)k * H_ + j];
            unsigned long long w2[4];
            PACK2(w2[0], wv.x); PACK2(w2[1], wv.y);
            PACK2(w2[2], wv.z); PACK2(w2[3], wv.w);
#pragma unroll
            for (int r = 0; r < 4; r++) {
                FMA2(a01[r], w2[r], h01);
                FMA2(a23[r], w2[r], h23);
            }
        }
        float ga[4][4];   // [gate][batch]
#pragma unroll
        for (int r = 0; r < 4; r++) {
            UNPACK2(ga[r][0], ga[r][1], a01[r]);
            UNPACK2(ga[r][2], ga[r][3], a23[r]);
        }
        float hnew[4];
#pragma unroll
        for (int b = 0; b < 4; b++) {
            float ig = 1.0f / (1.0f + expf(-ga[0][b]));
            float fg = 1.0f / (1.0f + expf(-ga[1][b]));
            float gg = tanhf(ga[2][b]);
            float og = 1.0f / (1.0f + expf(-ga[3][b]));
            cc[b] = fg * cc[b] + ig * gg;
            hnew[b] = og * tanhf(cc[b]);
        }
        *(float4*)&hsh[p ^ 1][j][0] = make_float4(hnew[0], hnew[1], hnew[2], hnew[3]);
        __syncthreads();
    }
#pragma unroll
    for (int b = 0; b < 4; b++) g_hn[b * H_ + j] = hsh[0][j][b];
}

// ---------------- K6: out[b, r] = hn[b,:]·f1_w[r,:] + f1_b[r] -------------------
__global__ void k_out(const float* __restrict__ f1_w, const float* __restrict__ f1_b) {
    __shared__ __align__(16) float hsh[B_ * H_];
    for (int i = threadIdx.x; i < B_ * H_; i += 256) hsh[i] = g_hn[i];
    __syncthreads();
    int warp = threadIdx.x >> 5, lane = threadIdx.x & 31;
    int r = blockIdx.x * 8 + warp;
    const float4* Wr = (const float4*)(f1_w + (size_t)r * H_);
    float a[B_] = {0.f, 0.f, 0.f, 0.f};
#pragma unroll
    for (int t = 0; t < 2; t++) {
        int idx = lane + 32 * t;
        float4 wv = Wr[idx];
#pragma unroll
        for (int b = 0; b < B_; b++) {
            float4 hv = *(const float4*)&hsh[b * H_ + idx * 4];
            a[b] += wv.x * hv.x + wv.y * hv.y + wv.z * hv.z + wv.w * hv.w;
        }
    }
#pragma unroll
    for (int b = 0; b < B_; b++) {
#pragma unroll
        for (int o = 16; o; o >>= 1) a[b] += __shfl_xor_sync(0xffffffffu, a[b], o);
    }
    if (lane == 0) {
        float bb = f1_b[r];
#pragma unroll
        for (int b = 0; b < B_; b++) g_out[(size_t)b * D_ + r] = a[b] + bb;
    }
}

// ---------------- K6c: s1[b,n], s2[b,n] -----------------------------------------
__global__ void k_s(const float* __restrict__ f2_w) {
    int idx = blockIdx.x * 256 + threadIdx.x;
    const float4* v4 = (const float4*)(g_out + (size_t)idx * FOUT_);
    const float4* w1 = (const float4*)(f2_w);
    const float4* w2 = (const float4*)(f2_w + FOUT_);
    float s1 = 0.f, s2 = 0.f;
#pragma unroll
    for (int t = 0; t < 8; t++) {
        float4 v = v4[t], a = w1[t], b = w2[t];
        s1 += v.x * a.x + v.y * a.y + v.z * a.z + v.w * a.w;
        s2 += v.x * b.x + v.y * b.y + v.z * b.z + v.w * b.w;
    }
    g_s1[idx] = s1;
    g_s2[idx] = s2;
}

// ---------------- K7: scores, keep mask, L1 row-normalize, write output ----------
__global__ void k_final(float* __restrict__ res, const float* __restrict__ f2_b) {
    __shared__ float s1s[N_], s2s[N_];
    __shared__ float wsum[8];
    __shared__ float total;
    int b = blockIdx.x >> 10;
    int i = blockIdx.x & 1023;
    for (int t = threadIdx.x; t < N_; t += 256) {
        s1s[t] = g_s1[b * N_ + t];
        s2s[t] = g_s2[b * N_ + t];
    }
    __syncthreads();
    float bias = f2_b[0];
    float s1i = s1s[i], s2i = s2s[i];
    float v[4];
    float asum = 0.f;
#pragma unroll
    for (int t = 0; t < 4; t++) {
        int j = threadIdx.x + t * 256;
        float sc = s1i + s2s[j] + bias;
        float st = s1s[j] + s2i + bias;
        float val;
        if (i == j) {
            val = sc;
        } else {
            bool keep = (i < j) ? (sc >= st && sc > 0.f) : (sc > st && sc >= 0.f);
            val = keep ? sc : 0.f;
        }
        v[t] = val;
        asum += fabsf(val);
    }
    int warp = threadIdx.x >> 5, lane = threadIdx.x & 31;
#pragma unroll
    for (int o = 16; o; o >>= 1) asum += __shfl_xor_sync(0xffffffffu, asum, o);
    if (lane == 0) wsum[warp] = asum;
    __syncthreads();
    if (threadIdx.x == 0) {
        float s = 0.f;
#pragma unroll
        for (int k = 0; k < 8; k++) s += wsum[k];
        total = s;
    }
    __syncthreads();
    float inv = 1.0f / fmaxf(total, 1e-12f);
    float* row = res + ((size_t)b * N_ + i) * N_;
#pragma unroll
    for (int t = 0; t < 4; t++) row[threadIdx.x + t * 256] = v[t] * inv;
}

// =================================================================================
extern "C" void kernel_launch(void* const* d_in, const int* in_sizes, int n_in,
                              void* d_out, int out_size) {
    const float* shots = (const float*)d_in[0];
    const float* node  = (const float*)d_in[1];
    // d_in[2] = 'a' (unused by reference)
    const float* gcn_w = (const float*)d_in[3];
    const float* w_ih  = (const float*)d_in[4];
    const float* w_hh  = (const float*)d_in[5];
    const float* b_ih  = (const float*)d_in[6];
    const float* b_hh  = (const float*)d_in[7];
    const float* f1_w  = (const float*)d_in[8];
    const float* f1_b  = (const float*)d_in[9];
    const float* f2_w  = (const float*)d_in[10];
    const float* f2_b  = (const float*)d_in[11];
    float* res = (float*)d_out;

    cudaFuncSetAttribute(k_gates, cudaFuncAttributeMaxDynamicSharedMemorySize, GATES_SMEM);

    k_whhT<<<dim3(32, 8), dim3(32, 8)>>>(w_hh);          // #1 (independent)
    k_degP<<<BW_ * N_ / 8, 256>>>(shots, node, gcn_w);   // #2
    k_gcn<<<dim3(BW_ * 8, KQ_), 64>>>(shots);            // #3
    k_xfin<<<D_ / 64, 256>>>();                          // #4
    k_gates<<<dim3(8, KC_), 192, GATES_SMEM>>>(w_ih);    // #5
    k_greduce<<<BW_ * 4 * H_ / 256, 256>>>(b_ih, b_hh);  // #6
    k_lstm<<<1, H_>>>();                                 // #7
    k_out<<<D_ / 8, 256>>>(f1_w, f1_b);                  // #8
    k_s<<<B_ * N_ / 256, 256>>>(f2_w);                   // #9
    k_final<<<B_ * N_, 256>>>(res, f2_b);                // #10
}

// round 14
// speedup vs baseline: 1.5250x; 1.5250x over previous
#include <cuda_runtime.h>
#include <cstdint>

// Problem constants
static constexpr int B_   = 4;
static constexpr int W_   = 12;
static constexpr int N_   = 1024;
static constexpr int FIN_ = 32;
static constexpr int FOUT_= 32;
static constexpr int H_   = 256;
static constexpr int BW_  = B_ * W_;        // 48
static constexpr int D_   = N_ * FOUT_;     // 32768
static constexpr int KC_  = 64;             // split-K chunks for gates GEMM (k=512 each)
static constexpr int KQ_  = 8;              // split-K for gcn GEMM (k=128 each)

// ---------------- packed f32x2 helpers ----------------
#define FMA2(acc, a, b) asm("fma.rn.f32x2 %0, %1, %2, %0;" : "+l"(acc) : "l"(a), "l"(b))
#define PACK2(d, f)     asm("mov.b64 %0, {%1, %1};" : "=l"(d) : "f"(f))
#define UNPACK2(lo, hi, d) asm("mov.b64 {%0, %1}, %2;" : "=f"(lo), "=f"(hi) : "l"(d))

// ---------------- cp.async helpers ----------------
__device__ __forceinline__ void cp16(uint32_t dst, const void* src) {
    asm volatile("cp.async.cg.shared.global [%0], [%1], 16;" :: "r"(dst), "l"(src));
}
#define CP_COMMIT() asm volatile("cp.async.commit_group;")
#define CP_WAIT1()  asm volatile("cp.async.wait_group 1;")
#define CP_WAIT0()  asm volatile("cp.async.wait_group 0;")

// ---------------- scratch (static device globals; no allocation) ----------------
__device__ float g_deg[BW_ * N_];
__device__ float g_P[(size_t)BW_ * N_ * FOUT_];
__device__ float g_xpart[(size_t)KQ_ * BW_ * N_ * FOUT_];   // gcn split-K partials
__device__ float g_XT[(size_t)D_ * BW_];                    // X transposed: [k][wb]
__device__ float g_part[(size_t)KC_ * BW_ * 4 * H_];        // gates split-K partials
__device__ float g_gates[BW_ * 4 * H_];
__device__ float g_whhT[(size_t)H_ * 4 * H_];               // [k][j*4+r] interleaved
__device__ float g_hn[B_ * H_];
__device__ float g_out[B_ * D_];
__device__ float g_s1[B_ * N_];
__device__ float g_s2[B_ * N_];

// ---------------- K0: transpose w_hh [4H][H] -> whhT [k][j*4+r] -----------------
// grid (32, 8), block (32, 8)
__global__ void k_whhT(const float* __restrict__ w_hh) {
    __shared__ float tile[32][33];
    int gb = blockIdx.x * 32;   // gate-row base (0..1023), never crosses 256 bnd
    int kb = blockIdx.y * 32;   // k base (0..255)
    int tx = threadIdx.x, ty = threadIdx.y;
#pragma unroll
    for (int i = 0; i < 32; i += 8)
        tile[ty + i][tx] = w_hh[(size_t)(gb + ty + i) * H_ + kb + tx];
    __syncthreads();
    int r = gb >> 8;            // gate index (0..3), same for all tx
    int jb = gb & 255;          // unit base
#pragma unroll
    for (int i = 0; i < 32; i += 8)
        g_whhT[(size_t)(kb + ty + i) * (4 * H_) + (jb + tx) * 4 + r] = tile[tx][ty + i];
}

// ---------------- K1: fused degree + P -------------------------------------------
__global__ void k_degP(const float* __restrict__ shots, const float* __restrict__ node,
                       const float* __restrict__ gcn_w) {
    __shared__ float gw[FIN_ * FOUT_];
    int r0 = blockIdx.x * 8;
    int w  = (r0 / N_) % W_;            // rows bw-major: bw = b*W + w
    for (int i = threadIdx.x; i < FIN_ * FOUT_; i += 256)
        gw[i] = gcn_w[(size_t)w * FIN_ * FOUT_ + i];
    __syncthreads();
    int warp = threadIdx.x >> 5, lane = threadIdx.x & 31;
    int r = r0 + warp;
    const float4* p = (const float4*)(shots + (size_t)r * N_);
    float s = 0.f;
#pragma unroll
    for (int i = 0; i < 8; i++) {
        float4 v = p[lane + 32 * i];
        s += v.x + v.y + v.z + v.w;
    }
#pragma unroll
    for (int o = 16; o; o >>= 1) s += __shfl_xor_sync(0xffffffffu, s, o);
    float d = 1.0f / sqrtf(1.0f + s);
    if (lane == 0) g_deg[r] = d;

    float nv = node[(size_t)r * FIN_ + lane];
    float acc = 0.f;
#pragma unroll
    for (int f = 0; f < FIN_; f++) {
        float x = __shfl_sync(0xffffffffu, nv, f);
        acc += x * gw[f * FOUT_ + lane];
    }
    g_P[(size_t)r * FOUT_ + lane] = d * acc;
}

// ---------------- K3: xpart[kq] = shots[n, kq-chunk] @ P[kq-chunk, :] ----------
static constexpr int AS_ = 292;   // A_shT row stride (floats)
__global__ __launch_bounds__(64) void k_gcn(const float* __restrict__ shots) {
    __shared__ __align__(16) float AT[16 * AS_];   // [kk][f(row)]
    __shared__ __align__(16) float PS[16 * 32];    // [kk][col]
    int bw = blockIdx.x >> 3;
    int n0 = (blockIdx.x & 7) << 7;      // * 128
    int kq = blockIdx.y;
    int t = threadIdx.x;
    int tx = t & 3;
    int ty = t >> 2;
    const float* Abase = shots + (size_t)bw * N_ * N_;
    const float* Pbase = g_P + (size_t)bw * N_ * FOUT_;

    unsigned long long acc[4][8];
#pragma unroll
    for (int i = 0; i < 4; i++)
#pragma unroll
        for (int j = 0; j < 8; j++) acc[i][j] = 0ull;

    const int r8 = ty * 8;
    const int fr = r8 + ((r8 >> 5) << 2);

    for (int k0 = kq * 128; k0 < kq * 128 + 128; k0 += 16) {
#pragma unroll
        for (int i = 0; i < 8; i++) {
            int idx = t + 64 * i;
            int rr = idx >> 2, q = idx & 3;
            float4 v = *(const float4*)(Abase + (size_t)(n0 + rr) * N_ + k0 + 4 * q);
            int f = rr + ((rr >> 5) << 2);
            AT[(4 * q + 0) * AS_ + f] = v.x;
            AT[(4 * q + 1) * AS_ + f] = v.y;
            AT[(4 * q + 2) * AS_ + f] = v.z;
            AT[(4 * q + 3) * AS_ + f] = v.w;
        }
#pragma unroll
        for (int i = 0; i < 2; i++) {
            int idx = t + 64 * i;
            int kk = idx >> 3, c = idx & 7;
            *(float4*)&PS[kk * 32 + 4 * c] =
                *(const float4*)(Pbase + (size_t)(k0 + kk) * 32 + 4 * c);
        }
        __syncthreads();
#pragma unroll 4
        for (int kk = 0; kk < 16; kk++) {
            ulonglong2 aA = *(const ulonglong2*)&AT[kk * AS_ + fr];
            ulonglong2 aB = *(const ulonglong2*)&AT[kk * AS_ + fr + 4];
            float4 p0 = *(const float4*)&PS[kk * 32 + tx * 8];
            float4 p1 = *(const float4*)&PS[kk * 32 + tx * 8 + 4];
            unsigned long long ap[4];
            ap[0] = aA.x; ap[1] = aA.y; ap[2] = aB.x; ap[3] = aB.y;
            unsigned long long bb[8];
            PACK2(bb[0], p0.x); PACK2(bb[1], p0.y); PACK2(bb[2], p0.z); PACK2(bb[3], p0.w);
            PACK2(bb[4], p1.x); PACK2(bb[5], p1.y); PACK2(bb[6], p1.z); PACK2(bb[7], p1.w);
#pragma unroll
            for (int i = 0; i < 4; i++)
#pragma unroll
                for (int j = 0; j < 8; j++) FMA2(acc[i][j], ap[i], bb[j]);
        }
        __syncthreads();
    }

    float* Xp = g_xpart + (size_t)kq * BW_ * N_ * FOUT_ + (size_t)bw * N_ * FOUT_;
#pragma unroll
    for (int i = 0; i < 4; i++) {
        int ne = n0 + r8 + 2 * i;
        float lo[8], hi[8];
#pragma unroll
        for (int j = 0; j < 8; j++) UNPACK2(lo[j], hi[j], acc[i][j]);
        float4 o0 = {lo[0], lo[1], lo[2], lo[3]};
        float4 o1 = {lo[4], lo[5], lo[6], lo[7]};
        float4 o2 = {hi[0], hi[1], hi[2], hi[3]};
        float4 o3 = {hi[4], hi[5], hi[6], hi[7]};
        *(float4*)(Xp + (size_t)ne * 32 + tx * 8) = o0;
        *(float4*)(Xp + (size_t)ne * 32 + tx * 8 + 4) = o1;
        *(float4*)(Xp + (size_t)(ne + 1) * 32 + tx * 8) = o2;
        *(float4*)(Xp + (size_t)(ne + 1) * 32 + tx * 8 + 4) = o3;
    }
}

// ---------------- K3f: XT[k][wb] = d[n]*(sum_kq xpart + P), smem-tiled transpose -
// 512 blocks x 256 thr; block handles 64 consecutive k-rows.
__global__ void k_xfin(void) {
    __shared__ float tile[64 * 49];    // [rr][wb'] (stride 49: conflict-free)
    int rt = blockIdx.x * 64;
    int t = threadIdx.x;
#pragma unroll 4
    for (int pass = 0; pass < 12; pass++) {
        int p = pass * 256 + t;
        int bw = p >> 6, rr = p & 63;
        int r = rt + rr;
        float s = g_P[(size_t)bw * D_ + r];
#pragma unroll
        for (int kq = 0; kq < KQ_; kq++)
            s += g_xpart[(size_t)kq * BW_ * D_ + (size_t)bw * D_ + r];
        s *= g_deg[bw * N_ + (r >> 5)];
        int w = bw % W_, b = bw / W_;
        tile[rr * 49 + (w * B_ + b)] = s;
    }
    __syncthreads();
#pragma unroll 4
    for (int pass = 0; pass < 12; pass++) {
        int o = pass * 256 + t;
        int rr = o / 48, c = o % 48;
        g_XT[(size_t)(rt + rr) * BW_ + c] = tile[rr * 49 + c];
    }
}

// ---------------- K4: gates_x = X @ w_ih^T  (dual cp.async, 4 blocks/SM) --------
static constexpr int WROW_ = 36;                  // W smem row stride (floats)
static constexpr int WBUF_ = 128 * WROW_;         // 4608 floats per buffer
static constexpr int XS_   = 52;                  // XT smem row stride
static constexpr int XBUF_ = 32 * XS_;            // 1664 floats per buffer
static constexpr int GATES_SMEM = (2 * WBUF_ + 2 * XBUF_) * 4;   // 50176 B

__global__ __launch_bounds__(192, 4) void k_gates(const float* __restrict__ w_ih) {
    extern __shared__ __align__(16) float sm[];
    float* WS = sm;                 // [2][128][36]
    float* XT = sm + 2 * WBUF_;     // [2][32][52]
    const int g0 = blockIdx.x * 128;
    const int kc = blockIdx.y;
    const int kbase = kc * 512;
    const int t = threadIdx.x;
    const int warp = t >> 5, gl = t & 31;
    const int wb0 = warp * 8;
    const uint32_t ws_smem = (uint32_t)__cvta_generic_to_shared(WS);
    const uint32_t xt_smem = (uint32_t)__cvta_generic_to_shared(XT);

    unsigned long long acc[4][4];
#pragma unroll
    for (int i = 0; i < 4; i++)
#pragma unroll
        for (int j = 0; j < 4; j++) acc[i][j] = 0ull;

#define STAGE(bufi, k0)                                                            \
    do {                                                                           \
        for (int idx = t; idx < 1024; idx += 192) {                                \
            int g = idx >> 3, q = idx & 7;                                         \
            cp16(ws_smem + ((bufi) * WBUF_ + g * WROW_ + 4 * q) * 4,               \
                 w_ih + (size_t)(g0 + g) * D_ + (k0) + 4 * q);                     \
        }                                                                          \
        for (int idx = t; idx < 384; idx += 192) {                                 \
            int kk = idx / 12, q = idx % 12;                                       \
            cp16(xt_smem + ((bufi) * XBUF_ + kk * XS_ + 4 * q) * 4,                \
                 g_XT + (size_t)((k0) + kk) * BW_ + 4 * q);                        \
        }                                                                          \
        CP_COMMIT();                                                               \
    } while (0)

    STAGE(0, kbase);

    for (int s = 0; s < 16; s++) {
        int buf = s & 1;
        __syncthreads();   // previous compute done -> other buffer free
        if (s < 15) {
            STAGE(buf ^ 1, kbase + 32 * (s + 1));
            CP_WAIT1();
        } else {
            CP_WAIT0();
        }
        __syncthreads();
        const float* WB = WS + buf * WBUF_;
        const float* XB = XT + buf * XBUF_;
#pragma unroll
        for (int kkc = 0; kkc < 8; kkc++) {
            unsigned long long ap[4][4];
#pragma unroll
            for (int kk = 0; kk < 4; kk++) {
                int krow = kkc * 4 + kk;
                ulonglong2 xA = *(const ulonglong2*)&XB[krow * XS_ + wb0];
                ulonglong2 xB2 = *(const ulonglong2*)&XB[krow * XS_ + wb0 + 4];
                ap[kk][0] = xA.x; ap[kk][1] = xA.y; ap[kk][2] = xB2.x; ap[kk][3] = xB2.y;
            }
#pragma unroll
            for (int j = 0; j < 4; j++) {
                float4 v = *(const float4*)&WB[(gl + 32 * j) * WROW_ + kkc * 4];
                float wf[4] = {v.x, v.y, v.z, v.w};
#pragma unroll
                for (int kk = 0; kk < 4; kk++) {
                    unsigned long long b2;
                    PACK2(b2, wf[kk]);
#pragma unroll
                    for (int i = 0; i < 4; i++) FMA2(acc[i][j], ap[kk][i], b2);
                }
            }
        }
    }
#undef STAGE

    // epilogue -> split-K partials
#pragma unroll
    for (int i = 0; i < 4; i++) {
#pragma unroll
        for (int j = 0; j < 4; j++) {
            float lo, hi;
            UNPACK2(lo, hi, acc[i][j]);
            int gcol = g0 + gl + 32 * j;
            g_part[((size_t)kc * BW_ + wb0 + 2 * i) * 1024 + gcol] = lo;
            g_part[((size_t)kc * BW_ + wb0 + 2 * i + 1) * 1024 + gcol] = hi;
        }
    }
}

// ---------------- K4r: reduce split-K + biases ----------------------------------
__global__ void k_greduce(const float* __restrict__ b_ih, const float* __restrict__ b_hh) {
    int i = blockIdx.x * 256 + threadIdx.x;   // 0..49151
    int g = i & 1023;
    float s = b_ih[g] + b_hh[g];
#pragma unroll 8
    for (int kc = 0; kc < KC_; kc++) s += g_part[(size_t)kc * BW_ * 1024 + i];
    g_gates[i] = s;
}

// ---------------- K5: fused 12-step LSTM (4 blocks, explicit depth-8 prefetch) --
// One block per batch (independent, no barrier). Thread j = hidden unit j.
// Weight stream: two 8-deep float4 register buffers; loads issued as a batch
// BEFORE the consuming phase -> guaranteed MLP=8. `&255` wraps tail prefetch.
__global__ __launch_bounds__(256) void k_lstm() {
    __shared__ __align__(16) float hsh[2][H_];
    int b = blockIdx.x;
    int j = threadIdx.x;
    float cc = 0.f;
    hsh[0][j] = 0.f;
    __syncthreads();
    const float4* w4 = (const float4*)g_whhT;   // [k][j]: 4 gate weights (i,f,g,o)

    for (int w = 0; w < W_; w++) {
        int p = w & 1;
        const float* gx = g_gates + ((size_t)(w * B_ + b)) * 4 * H_;
        float a0 = gx[j], a1 = gx[H_ + j], a2 = gx[2 * H_ + j], a3 = gx[3 * H_ + j];

        float4 bufA[8], bufB[8];
#pragma unroll
        for (int u = 0; u < 8; u++) bufA[u] = w4[(size_t)u * H_ + j];

#pragma unroll
        for (int kb = 0; kb < 256; kb += 16) {
            // prefetch next 8 (k = kb+8 .. kb+15)
#pragma unroll
            for (int u = 0; u < 8; u++)
                bufB[u] = w4[(size_t)((kb + 8 + u) & 255) * H_ + j];
            // consume bufA (k = kb .. kb+7)
#pragma unroll
            for (int u = 0; u < 8; u++) {
                float hk = hsh[p][kb + u];
                a0 += bufA[u].x * hk;
                a1 += bufA[u].y * hk;
                a2 += bufA[u].z * hk;
                a3 += bufA[u].w * hk;
            }
            // prefetch following 8 (k = kb+16 .. kb+23, wrapped at end)
#pragma unroll
            for (int u = 0; u < 8; u++)
                bufA[u] = w4[(size_t)((kb + 16 + u) & 255) * H_ + j];
            // consume bufB (k = kb+8 .. kb+15)
#pragma unroll
            for (int u = 0; u < 8; u++) {
                float hk = hsh[p][kb + 8 + u];
                a0 += bufB[u].x * hk;
                a1 += bufB[u].y * hk;
                a2 += bufB[u].z * hk;
                a3 += bufB[u].w * hk;
            }
        }
        float ig = 1.0f / (1.0f + expf(-a0));
        float fg = 1.0f / (1.0f + expf(-a1));
        float gg = tanhf(a2);
        float og = 1.0f / (1.0f + expf(-a3));
        cc = fg * cc + ig * gg;
        hsh[p ^ 1][j] = og * tanhf(cc);
        __syncthreads();
    }
    g_hn[b * H_ + j] = hsh[0][j];   // after 12 steps result is in buffer 0
}

// ---------------- K6: out[b, r] = hn[b,:]·f1_w[r,:] + f1_b[r] -------------------
__global__ void k_out(const float* __restrict__ f1_w, const float* __restrict__ f1_b) {
    __shared__ __align__(16) float hsh[B_ * H_];
    for (int i = threadIdx.x; i < B_ * H_; i += 256) hsh[i] = g_hn[i];
    __syncthreads();
    int warp = threadIdx.x >> 5, lane = threadIdx.x & 31;
    int r = blockIdx.x * 8 + warp;
    const float4* Wr = (const float4*)(f1_w + (size_t)r * H_);
    float a[B_] = {0.f, 0.f, 0.f, 0.f};
#pragma unroll
    for (int t = 0; t < 2; t++) {
        int idx = lane + 32 * t;
        float4 wv = Wr[idx];
#pragma unroll
        for (int b = 0; b < B_; b++) {
            float4 hv = *(const float4*)&hsh[b * H_ + idx * 4];
            a[b] += wv.x * hv.x + wv.y * hv.y + wv.z * hv.z + wv.w * hv.w;
        }
    }
#pragma unroll
    for (int b = 0; b < B_; b++) {
#pragma unroll
        for (int o = 16; o; o >>= 1) a[b] += __shfl_xor_sync(0xffffffffu, a[b], o);
    }
    if (lane == 0) {
        float bb = f1_b[r];
#pragma unroll
        for (int b = 0; b < B_; b++) g_out[(size_t)b * D_ + r] = a[b] + bb;
    }
}

// ---------------- K6c: s1[b,n], s2[b,n] -----------------------------------------
__global__ void k_s(const float* __restrict__ f2_w) {
    int idx = blockIdx.x * 256 + threadIdx.x;
    const float4* v4 = (const float4*)(g_out + (size_t)idx * FOUT_);
    const float4* w1 = (const float4*)(f2_w);
    const float4* w2 = (const float4*)(f2_w + FOUT_);
    float s1 = 0.f, s2 = 0.f;
#pragma unroll
    for (int t = 0; t < 8; t++) {
        float4 v = v4[t], a = w1[t], b = w2[t];
        s1 += v.x * a.x + v.y * a.y + v.z * a.z + v.w * a.w;
        s2 += v.x * b.x + v.y * b.y + v.z * b.z + v.w * b.w;
    }
    g_s1[idx] = s1;
    g_s2[idx] = s2;
}

// ---------------- K7: scores, keep mask, L1 row-normalize, write output ----------
__global__ void k_final(float* __restrict__ res, const float* __restrict__ f2_b) {
    __shared__ float s1s[N_], s2s[N_];
    __shared__ float wsum[8];
    __shared__ float total;
    int b = blockIdx.x >> 10;
    int i = blockIdx.x & 1023;
    for (int t = threadIdx.x; t < N_; t += 256) {
        s1s[t] = g_s1[b * N_ + t];
        s2s[t] = g_s2[b * N_ + t];
    }
    __syncthreads();
    float bias = f2_b[0];
    float s1i = s1s[i], s2i = s2s[i];
    float v[4];
    float asum = 0.f;
#pragma unroll
    for (int t = 0; t < 4; t++) {
        int j = threadIdx.x + t * 256;
        float sc = s1i + s2s[j] + bias;
        float st = s1s[j] + s2i + bias;
        float val;
        if (i == j) {
            val = sc;
        } else {
            bool keep = (i < j) ? (sc >= st && sc > 0.f) : (sc > st && sc >= 0.f);
            val = keep ? sc : 0.f;
        }
        v[t] = val;
        asum += fabsf(val);
    }
    int warp = threadIdx.x >> 5, lane = threadIdx.x & 31;
#pragma unroll
    for (int o = 16; o; o >>= 1) asum += __shfl_xor_sync(0xffffffffu, asum, o);
    if (lane == 0) wsum[warp] = asum;
    __syncthreads();
    if (threadIdx.x == 0) {
        float s = 0.f;
#pragma unroll
        for (int k = 0; k < 8; k++) s += wsum[k];
        total = s;
    }
    __syncthreads();
    float inv = 1.0f / fmaxf(total, 1e-12f);
    float* row = res + ((size_t)b * N_ + i) * N_;
#pragma unroll
    for (int t = 0; t < 4; t++) row[threadIdx.x + t * 256] = v[t] * inv;
}

// =================================================================================
extern "C" void kernel_launch(void* const* d_in, const int* in_sizes, int n_in,
                              void* d_out, int out_size) {
    const float* shots = (const float*)d_in[0];
    const float* node  = (const float*)d_in[1];
    // d_in[2] = 'a' (unused by reference)
    const float* gcn_w = (const float*)d_in[3];
    const float* w_ih  = (const float*)d_in[4];
    const float* w_hh  = (const float*)d_in[5];
    const float* b_ih  = (const float*)d_in[6];
    const float* b_hh  = (const float*)d_in[7];
    const float* f1_w  = (const float*)d_in[8];
    const float* f1_b  = (const float*)d_in[9];
    const float* f2_w  = (const float*)d_in[10];
    const float* f2_b  = (const float*)d_in[11];
    float* res = (float*)d_out;

    cudaFuncSetAttribute(k_gates, cudaFuncAttributeMaxDynamicSharedMemorySize, GATES_SMEM);

    k_whhT<<<dim3(32, 8), dim3(32, 8)>>>(w_hh);          // #1 (independent)
    k_degP<<<BW_ * N_ / 8, 256>>>(shots, node, gcn_w);   // #2
    k_gcn<<<dim3(BW_ * 8, KQ_), 64>>>(shots);            // #3
    k_xfin<<<D_ / 64, 256>>>();                          // #4
    k_gates<<<dim3(8, KC_), 192, GATES_SMEM>>>(w_ih);    // #5
    k_greduce<<<BW_ * 4 * H_ / 256, 256>>>(b_ih, b_hh);  // #6
    k_lstm<<<B_, H_>>>();                                // #7
    k_out<<<D_ / 8, 256>>>(f1_w, f1_b);                  // #8
    k_s<<<B_ * N_ / 256, 256>>>(f2_w);                   // #9
    k_final<<<B_ * N_, 256>>>(res, f2_b);                // #10
}

// round 15
// speedup vs baseline: 1.8870x; 1.2374x over previous
#include <cuda_runtime.h>
#include <cstdint>

// Problem constants
static constexpr int B_   = 4;
static constexpr int W_   = 12;
static constexpr int N_   = 1024;
static constexpr int FIN_ = 32;
static constexpr int FOUT_= 32;
static constexpr int H_   = 256;
static constexpr int BW_  = B_ * W_;        // 48
static constexpr int D_   = N_ * FOUT_;     // 32768
static constexpr int KC_  = 64;             // split-K chunks for gates GEMM (k=512 each)
static constexpr int KQ_  = 8;              // split-K for gcn GEMM (k=128 each)

// ---------------- packed f32x2 helpers ----------------
#define FMA2(acc, a, b) asm("fma.rn.f32x2 %0, %1, %2, %0;" : "+l"(acc) : "l"(a), "l"(b))
#define PACK2(d, f)     asm("mov.b64 %0, {%1, %1};" : "=l"(d) : "f"(f))
#define UNPACK2(lo, hi, d) asm("mov.b64 {%0, %1}, %2;" : "=f"(lo), "=f"(hi) : "l"(d))

// ---------------- cp.async helpers ----------------
__device__ __forceinline__ void cp16(uint32_t dst, const void* src) {
    asm volatile("cp.async.cg.shared.global [%0], [%1], 16;" :: "r"(dst), "l"(src));
}
#define CP_COMMIT() asm volatile("cp.async.commit_group;")
#define CP_WAIT1()  asm volatile("cp.async.wait_group 1;")
#define CP_WAIT0()  asm volatile("cp.async.wait_group 0;")

// ---------------- scratch (static device globals; no allocation) ----------------
__device__ float g_deg[BW_ * N_];
__device__ float g_P[(size_t)BW_ * N_ * FOUT_];
__device__ float g_xpart[(size_t)KQ_ * BW_ * N_ * FOUT_];   // gcn split-K partials
__device__ float g_XT[(size_t)D_ * BW_];                    // X transposed: [k][wb]
__device__ float g_part[(size_t)KC_ * BW_ * 4 * H_];        // gates split-K partials
__device__ float g_gates[BW_ * 4 * H_];
__device__ float g_whhT[(size_t)H_ * 4 * H_];               // [k][j*4+r] interleaved
__device__ float g_hx[B_ * H_];                             // lstm h exchange
__device__ int   g_lcnt[B_];                                // lstm per-batch counters
__device__ float g_hn[B_ * H_];
__device__ float g_out[B_ * D_];
__device__ float g_s1[B_ * N_];
__device__ float g_s2[B_ * N_];

// ---------------- K0: transpose w_hh [4H][H] -> whhT [k][j*4+r]; reset counters --
// grid (32, 8), block (32, 8)
__global__ void k_whhT(const float* __restrict__ w_hh) {
    __shared__ float tile[32][33];
    int gb = blockIdx.x * 32;   // gate-row base (0..1023), never crosses 256 bnd
    int kb = blockIdx.y * 32;   // k base (0..255)
    int tx = threadIdx.x, ty = threadIdx.y;
    if (blockIdx.x == 0 && blockIdx.y == 0 && ty == 0 && tx < B_) g_lcnt[tx] = 0;
#pragma unroll
    for (int i = 0; i < 32; i += 8)
        tile[ty + i][tx] = w_hh[(size_t)(gb + ty + i) * H_ + kb + tx];
    __syncthreads();
    int r = gb >> 8;            // gate index (0..3), same for all tx
    int jb = gb & 255;          // unit base
#pragma unroll
    for (int i = 0; i < 32; i += 8)
        g_whhT[(size_t)(kb + ty + i) * (4 * H_) + (jb + tx) * 4 + r] = tile[tx][ty + i];
}

// ---------------- K1: fused degree + P -------------------------------------------
__global__ void k_degP(const float* __restrict__ shots, const float* __restrict__ node,
                       const float* __restrict__ gcn_w) {
    __shared__ float gw[FIN_ * FOUT_];
    int r0 = blockIdx.x * 8;
    int w  = (r0 / N_) % W_;            // rows bw-major: bw = b*W + w
    for (int i = threadIdx.x; i < FIN_ * FOUT_; i += 256)
        gw[i] = gcn_w[(size_t)w * FIN_ * FOUT_ + i];
    __syncthreads();
    int warp = threadIdx.x >> 5, lane = threadIdx.x & 31;
    int r = r0 + warp;
    const float4* p = (const float4*)(shots + (size_t)r * N_);
    float s = 0.f;
#pragma unroll
    for (int i = 0; i < 8; i++) {
        float4 v = p[lane + 32 * i];
        s += v.x + v.y + v.z + v.w;
    }
#pragma unroll
    for (int o = 16; o; o >>= 1) s += __shfl_xor_sync(0xffffffffu, s, o);
    float d = 1.0f / sqrtf(1.0f + s);
    if (lane == 0) g_deg[r] = d;

    float nv = node[(size_t)r * FIN_ + lane];
    float acc = 0.f;
#pragma unroll
    for (int f = 0; f < FIN_; f++) {
        float x = __shfl_sync(0xffffffffu, nv, f);
        acc += x * gw[f * FOUT_ + lane];
    }
    g_P[(size_t)r * FOUT_ + lane] = d * acc;
}

// ---------------- K3: xpart[kq] = shots[n, kq-chunk] @ P[kq-chunk, :] ----------
static constexpr int AS_ = 292;   // A_shT row stride (floats)
__global__ __launch_bounds__(64) void k_gcn(const float* __restrict__ shots) {
    __shared__ __align__(16) float AT[16 * AS_];   // [kk][f(row)]
    __shared__ __align__(16) float PS[16 * 32];    // [kk][col]
    int bw = blockIdx.x >> 3;
    int n0 = (blockIdx.x & 7) << 7;      // * 128
    int kq = blockIdx.y;
    int t = threadIdx.x;
    int tx = t & 3;
    int ty = t >> 2;
    const float* Abase = shots + (size_t)bw * N_ * N_;
    const float* Pbase = g_P + (size_t)bw * N_ * FOUT_;

    unsigned long long acc[4][8];
#pragma unroll
    for (int i = 0; i < 4; i++)
#pragma unroll
        for (int j = 0; j < 8; j++) acc[i][j] = 0ull;

    const int r8 = ty * 8;
    const int fr = r8 + ((r8 >> 5) << 2);

    for (int k0 = kq * 128; k0 < kq * 128 + 128; k0 += 16) {
#pragma unroll
        for (int i = 0; i < 8; i++) {
            int idx = t + 64 * i;
            int rr = idx >> 2, q = idx & 3;
            float4 v = *(const float4*)(Abase + (size_t)(n0 + rr) * N_ + k0 + 4 * q);
            int f = rr + ((rr >> 5) << 2);
            AT[(4 * q + 0) * AS_ + f] = v.x;
            AT[(4 * q + 1) * AS_ + f] = v.y;
            AT[(4 * q + 2) * AS_ + f] = v.z;
            AT[(4 * q + 3) * AS_ + f] = v.w;
        }
#pragma unroll
        for (int i = 0; i < 2; i++) {
            int idx = t + 64 * i;
            int kk = idx >> 3, c = idx & 7;
            *(float4*)&PS[kk * 32 + 4 * c] =
                *(const float4*)(Pbase + (size_t)(k0 + kk) * 32 + 4 * c);
        }
        __syncthreads();
#pragma unroll 4
        for (int kk = 0; kk < 16; kk++) {
            ulonglong2 aA = *(const ulonglong2*)&AT[kk * AS_ + fr];
            ulonglong2 aB = *(const ulonglong2*)&AT[kk * AS_ + fr + 4];
            float4 p0 = *(const float4*)&PS[kk * 32 + tx * 8];
            float4 p1 = *(const float4*)&PS[kk * 32 + tx * 8 + 4];
            unsigned long long ap[4];
            ap[0] = aA.x; ap[1] = aA.y; ap[2] = aB.x; ap[3] = aB.y;
            unsigned long long bb[8];
            PACK2(bb[0], p0.x); PACK2(bb[1], p0.y); PACK2(bb[2], p0.z); PACK2(bb[3], p0.w);
            PACK2(bb[4], p1.x); PACK2(bb[5], p1.y); PACK2(bb[6], p1.z); PACK2(bb[7], p1.w);
#pragma unroll
            for (int i = 0; i < 4; i++)
#pragma unroll
                for (int j = 0; j < 8; j++) FMA2(acc[i][j], ap[i], bb[j]);
        }
        __syncthreads();
    }

    float* Xp = g_xpart + (size_t)kq * BW_ * N_ * FOUT_ + (size_t)bw * N_ * FOUT_;
#pragma unroll
    for (int i = 0; i < 4; i++) {
        int ne = n0 + r8 + 2 * i;
        float lo[8], hi[8];
#pragma unroll
        for (int j = 0; j < 8; j++) UNPACK2(lo[j], hi[j], acc[i][j]);
        float4 o0 = {lo[0], lo[1], lo[2], lo[3]};
        float4 o1 = {lo[4], lo[5], lo[6], lo[7]};
        float4 o2 = {hi[0], hi[1], hi[2], hi[3]};
        float4 o3 = {hi[4], hi[5], hi[6], hi[7]};
        *(float4*)(Xp + (size_t)ne * 32 + tx * 8) = o0;
        *(float4*)(Xp + (size_t)ne * 32 + tx * 8 + 4) = o1;
        *(float4*)(Xp + (size_t)(ne + 1) * 32 + tx * 8) = o2;
        *(float4*)(Xp + (size_t)(ne + 1) * 32 + tx * 8 + 4) = o3;
    }
}

// ---------------- K3f: XT[k][wb] = d[n]*(sum_kq xpart + P), smem-tiled transpose -
// 512 blocks x 256 thr; block handles 64 consecutive k-rows.
__global__ void k_xfin(void) {
    __shared__ float tile[64 * 49];    // [rr][wb'] (stride 49: conflict-free)
    int rt = blockIdx.x * 64;
    int t = threadIdx.x;
#pragma unroll 4
    for (int pass = 0; pass < 12; pass++) {
        int p = pass * 256 + t;
        int bw = p >> 6, rr = p & 63;
        int r = rt + rr;
        float s = g_P[(size_t)bw * D_ + r];
#pragma unroll
        for (int kq = 0; kq < KQ_; kq++)
            s += g_xpart[(size_t)kq * BW_ * D_ + (size_t)bw * D_ + r];
        s *= g_deg[bw * N_ + (r >> 5)];
        int w = bw % W_, b = bw / W_;
        tile[rr * 49 + (w * B_ + b)] = s;
    }
    __syncthreads();
#pragma unroll 4
    for (int pass = 0; pass < 12; pass++) {
        int o = pass * 256 + t;
        int rr = o / 48, c = o % 48;
        g_XT[(size_t)(rt + rr) * BW_ + c] = tile[rr * 49 + c];
    }
}

// ---------------- K4: gates_x = X @ w_ih^T  (dual cp.async, 4 blocks/SM) --------
static constexpr int WROW_ = 36;                  // W smem row stride (floats)
static constexpr int WBUF_ = 128 * WROW_;         // 4608 floats per buffer
static constexpr int XS_   = 52;                  // XT smem row stride
static constexpr int XBUF_ = 32 * XS_;            // 1664 floats per buffer
static constexpr int GATES_SMEM = (2 * WBUF_ + 2 * XBUF_) * 4;   // 50176 B

__global__ __launch_bounds__(192, 4) void k_gates(const float* __restrict__ w_ih) {
    extern __shared__ __align__(16) float sm[];
    float* WS = sm;                 // [2][128][36]
    float* XT = sm + 2 * WBUF_;     // [2][32][52]
    const int g0 = blockIdx.x * 128;
    const int kc = blockIdx.y;
    const int kbase = kc * 512;
    const int t = threadIdx.x;
    const int warp = t >> 5, gl = t & 31;
    const int wb0 = warp * 8;
    const uint32_t ws_smem = (uint32_t)__cvta_generic_to_shared(WS);
    const uint32_t xt_smem = (uint32_t)__cvta_generic_to_shared(XT);

    unsigned long long acc[4][4];
#pragma unroll
    for (int i = 0; i < 4; i++)
#pragma unroll
        for (int j = 0; j < 4; j++) acc[i][j] = 0ull;

#define STAGE(bufi, k0)                                                            \
    do {                                                                           \
        for (int idx = t; idx < 1024; idx += 192) {                                \
            int g = idx >> 3, q = idx & 7;                                         \
            cp16(ws_smem + ((bufi) * WBUF_ + g * WROW_ + 4 * q) * 4,               \
                 w_ih + (size_t)(g0 + g) * D_ + (k0) + 4 * q);                     \
        }                                                                          \
        for (int idx = t; idx < 384; idx += 192) {                                 \
            int kk = idx / 12, q = idx % 12;                                       \
            cp16(xt_smem + ((bufi) * XBUF_ + kk * XS_ + 4 * q) * 4,                \
                 g_XT + (size_t)((k0) + kk) * BW_ + 4 * q);                        \
        }                                                                          \
        CP_COMMIT();                                                               \
    } while (0)

    STAGE(0, kbase);

    for (int s = 0; s < 16; s++) {
        int buf = s & 1;
        __syncthreads();   // previous compute done -> other buffer free
        if (s < 15) {
            STAGE(buf ^ 1, kbase + 32 * (s + 1));
            CP_WAIT1();
        } else {
            CP_WAIT0();
        }
        __syncthreads();
        const float* WB = WS + buf * WBUF_;
        const float* XB = XT + buf * XBUF_;
#pragma unroll
        for (int kkc = 0; kkc < 8; kkc++) {
            unsigned long long ap[4][4];
#pragma unroll
            for (int kk = 0; kk < 4; kk++) {
                int krow = kkc * 4 + kk;
                ulonglong2 xA = *(const ulonglong2*)&XB[krow * XS_ + wb0];
                ulonglong2 xB2 = *(const ulonglong2*)&XB[krow * XS_ + wb0 + 4];
                ap[kk][0] = xA.x; ap[kk][1] = xA.y; ap[kk][2] = xB2.x; ap[kk][3] = xB2.y;
            }
#pragma unroll
            for (int j = 0; j < 4; j++) {
                float4 v = *(const float4*)&WB[(gl + 32 * j) * WROW_ + kkc * 4];
                float wf[4] = {v.x, v.y, v.z, v.w};
#pragma unroll
                for (int kk = 0; kk < 4; kk++) {
                    unsigned long long b2;
                    PACK2(b2, wf[kk]);
#pragma unroll
                    for (int i = 0; i < 4; i++) FMA2(acc[i][j], ap[kk][i], b2);
                }
            }
        }
    }
#undef STAGE

    // epilogue -> split-K partials
#pragma unroll
    for (int i = 0; i < 4; i++) {
#pragma unroll
        for (int j = 0; j < 4; j++) {
            float lo, hi;
            UNPACK2(lo, hi, acc[i][j]);
            int gcol = g0 + gl + 32 * j;
            g_part[((size_t)kc * BW_ + wb0 + 2 * i) * 1024 + gcol] = lo;
            g_part[((size_t)kc * BW_ + wb0 + 2 * i + 1) * 1024 + gcol] = hi;
        }
    }
}

// ---------------- K4r: reduce split-K + biases ----------------------------------
__global__ void k_greduce(const float* __restrict__ b_ih, const float* __restrict__ b_hh) {
    int i = blockIdx.x * 256 + threadIdx.x;   // 0..49151
    int g = i & 1023;
    float s = b_ih[g] + b_hh[g];
#pragma unroll 8
    for (int kc = 0; kc < KC_; kc++) s += g_part[(size_t)kc * BW_ * 1024 + i];
    g_gates[i] = s;
}

// ---------------- K5: fused 12-step LSTM (16 blocks: 4 batches x 4 j-quarters) --
// Block (jq, b): computes units j in [jq*64, jq*64+64). 256 threads:
// warp w -> (k-quarter = w>>1, j-half = w&1); lane = j offset (coalesced loads).
// Partials reduced via smem; h exchanged across the batch's 4 blocks via
// st.cg + release/acquire counter. Weights/SM/step = 256 KB (4x less than R14).
__global__ __launch_bounds__(256) void k_lstm() {
    __shared__ __align__(16) float hsh[H_];
    __shared__ float part[4][64][4];   // [kq][j_local][gate]
    int jq = blockIdx.x;
    int b  = blockIdx.y;
    int t = threadIdx.x;
    int wwarp = t >> 5, lane = t & 31;
    int kq = wwarp >> 1;                   // 0..3 (64 k each)
    int jl = (wwarp & 1) * 32 + lane;      // 0..63 local unit
    int jglob = jq * 64 + jl;
    const float4* wp = (const float4*)g_whhT + (size_t)(kq * 64) * H_ + jglob;
    float cc = 0.f;                        // finalizer state (t < 64)
    hsh[t] = 0.f;
    __syncthreads();

    for (int w = 0; w < W_; w++) {
        // ---- partial gate sums over this thread's 64 k ----
        float a0 = 0.f, a1 = 0.f, a2 = 0.f, a3 = 0.f;
        float4 bufA[8], bufB[8];
#pragma unroll
        for (int u = 0; u < 8; u++) bufA[u] = wp[(size_t)u * H_];
#pragma unroll
        for (int kb = 0; kb < 64; kb += 16) {
#pragma unroll
            for (int u = 0; u < 8; u++)
                bufB[u] = wp[(size_t)((kb + 8 + u) & 63) * H_];
#pragma unroll
            for (int u = 0; u < 8; u++) {
                float hk = hsh[kq * 64 + kb + u];
                a0 += bufA[u].x * hk;
                a1 += bufA[u].y * hk;
                a2 += bufA[u].z * hk;
                a3 += bufA[u].w * hk;
            }
#pragma unroll
            for (int u = 0; u < 8; u++)
                bufA[u] = wp[(size_t)((kb + 16 + u) & 63) * H_];
#pragma unroll
            for (int u = 0; u < 8; u++) {
                float hk = hsh[kq * 64 + kb + 8 + u];
                a0 += bufB[u].x * hk;
                a1 += bufB[u].y * hk;
                a2 += bufB[u].z * hk;
                a3 += bufB[u].w * hk;
            }
        }
        part[kq][jl][0] = a0;
        part[kq][jl][1] = a1;
        part[kq][jl][2] = a2;
        part[kq][jl][3] = a3;
        __syncthreads();

        // ---- finalize (threads 0..63), publish h ----
        if (t < 64) {
            int j = jq * 64 + t;
            const float* gx = g_gates + ((size_t)(w * B_ + b)) * 4 * H_;
            float s0 = gx[j]           + part[0][t][0] + part[1][t][0] + part[2][t][0] + part[3][t][0];
            float s1 = gx[H_ + j]      + part[0][t][1] + part[1][t][1] + part[2][t][1] + part[3][t][1];
            float s2 = gx[2 * H_ + j]  + part[0][t][2] + part[1][t][2] + part[2][t][2] + part[3][t][2];
            float s3 = gx[3 * H_ + j]  + part[0][t][3] + part[1][t][3] + part[2][t][3] + part[3][t][3];
            float ig = 1.0f / (1.0f + expf(-s0));
            float fg = 1.0f / (1.0f + expf(-s1));
            float gg = tanhf(s2);
            float og = 1.0f / (1.0f + expf(-s3));
            cc = fg * cc + ig * gg;
            float hv = og * tanhf(cc);
            asm volatile("st.global.cg.f32 [%0], %1;" :: "l"(&g_hx[b * H_ + j]), "f"(hv));
        }
        __syncthreads();   // all finalizer stores issued before the count

        // ---- 4-block (per batch) barrier ----
        if (t == 0) {
            int target = 4 * (w + 1);
            asm volatile("red.release.gpu.global.add.s32 [%0], 1;" :: "l"(&g_lcnt[b]));
            int v;
            do {
                asm volatile("ld.acquire.gpu.global.s32 %0, [%1];" : "=r"(v) : "l"(&g_lcnt[b]));
            } while (v < target);
        }
        __syncthreads();

        // ---- reload full h ----
        float hv;
        asm volatile("ld.global.cg.f32 %0, [%1];" : "=f"(hv) : "l"(&g_hx[b * H_ + t]));
        hsh[t] = hv;
        __syncthreads();
    }
    if (jq == 0) g_hn[b * H_ + t] = hsh[t];
}

// ---------------- K6: out[b, r] = hn[b,:]·f1_w[r,:] + f1_b[r] -------------------
__global__ void k_out(const float* __restrict__ f1_w, const float* __restrict__ f1_b) {
    __shared__ __align__(16) float hsh[B_ * H_];
    for (int i = threadIdx.x; i < B_ * H_; i += 256) hsh[i] = g_hn[i];
    __syncthreads();
    int warp = threadIdx.x >> 5, lane = threadIdx.x & 31;
    int r = blockIdx.x * 8 + warp;
    const float4* Wr = (const float4*)(f1_w + (size_t)r * H_);
    float a[B_] = {0.f, 0.f, 0.f, 0.f};
#pragma unroll
    for (int t = 0; t < 2; t++) {
        int idx = lane + 32 * t;
        float4 wv = Wr[idx];
#pragma unroll
        for (int b = 0; b < B_; b++) {
            float4 hv = *(const float4*)&hsh[b * H_ + idx * 4];
            a[b] += wv.x * hv.x + wv.y * hv.y + wv.z * hv.z + wv.w * hv.w;
        }
    }
#pragma unroll
    for (int b = 0; b < B_; b++) {
#pragma unroll
        for (int o = 16; o; o >>= 1) a[b] += __shfl_xor_sync(0xffffffffu, a[b], o);
    }
    if (lane == 0) {
        float bb = f1_b[r];
#pragma unroll
        for (int b = 0; b < B_; b++) g_out[(size_t)b * D_ + r] = a[b] + bb;
    }
}

// ---------------- K6c: s1[b,n], s2[b,n] -----------------------------------------
__global__ void k_s(const float* __restrict__ f2_w) {
    int idx = blockIdx.x * 256 + threadIdx.x;
    const float4* v4 = (const float4*)(g_out + (size_t)idx * FOUT_);
    const float4* w1 = (const float4*)(f2_w);
    const float4* w2 = (const float4*)(f2_w + FOUT_);
    float s1 = 0.f, s2 = 0.f;
#pragma unroll
    for (int t = 0; t < 8; t++) {
        float4 v = v4[t], a = w1[t], b = w2[t];
        s1 += v.x * a.x + v.y * a.y + v.z * a.z + v.w * a.w;
        s2 += v.x * b.x + v.y * b.y + v.z * b.z + v.w * b.w;
    }
    g_s1[idx] = s1;
    g_s2[idx] = s2;
}

// ---------------- K7: scores, keep mask, L1 row-normalize, write output ----------
__global__ void k_final(float* __restrict__ res, const float* __restrict__ f2_b) {
    __shared__ float s1s[N_], s2s[N_];
    __shared__ float wsum[8];
    __shared__ float total;
    int b = blockIdx.x >> 10;
    int i = blockIdx.x & 1023;
    for (int t = threadIdx.x; t < N_; t += 256) {
        s1s[t] = g_s1[b * N_ + t];
        s2s[t] = g_s2[b * N_ + t];
    }
    __syncthreads();
    float bias = f2_b[0];
    float s1i = s1s[i], s2i = s2s[i];
    float v[4];
    float asum = 0.f;
#pragma unroll
    for (int t = 0; t < 4; t++) {
        int j = threadIdx.x + t * 256;
        float sc = s1i + s2s[j] + bias;
        float st = s1s[j] + s2i + bias;
        float val;
        if (i == j) {
            val = sc;
        } else {
            bool keep = (i < j) ? (sc >= st && sc > 0.f) : (sc > st && sc >= 0.f);
            val = keep ? sc : 0.f;
        }
        v[t] = val;
        asum += fabsf(val);
    }
    int warp = threadIdx.x >> 5, lane = threadIdx.x & 31;
#pragma unroll
    for (int o = 16; o; o >>= 1) asum += __shfl_xor_sync(0xffffffffu, asum, o);
    if (lane == 0) wsum[warp] = asum;
    __syncthreads();
    if (threadIdx.x == 0) {
        float s = 0.f;
#pragma unroll
        for (int k = 0; k < 8; k++) s += wsum[k];
        total = s;
    }
    __syncthreads();
    float inv = 1.0f / fmaxf(total, 1e-12f);
    float* row = res + ((size_t)b * N_ + i) * N_;
#pragma unroll
    for (int t = 0; t < 4; t++) row[threadIdx.x + t * 256] = v[t] * inv;
}

// =================================================================================
extern "C" void kernel_launch(void* const* d_in, const int* in_sizes, int n_in,
                              void* d_out, int out_size) {
    const float* shots = (const float*)d_in[0];
    const float* node  = (const float*)d_in[1];
    // d_in[2] = 'a' (unused by reference)
    const float* gcn_w = (const float*)d_in[3];
    const float* w_ih  = (const float*)d_in[4];
    const float* w_hh  = (const float*)d_in[5];
    const float* b_ih  = (const float*)d_in[6];
    const float* b_hh  = (const float*)d_in[7];
    const float* f1_w  = (const float*)d_in[8];
    const float* f1_b  = (const float*)d_in[9];
    const float* f2_w  = (const float*)d_in[10];
    const float* f2_b  = (const float*)d_in[11];
    float* res = (float*)d_out;

    cudaFuncSetAttribute(k_gates, cudaFuncAttributeMaxDynamicSharedMemorySize, GATES_SMEM);

    k_whhT<<<dim3(32, 8), dim3(32, 8)>>>(w_hh);          // #1 (also resets g_lcnt)
    k_degP<<<BW_ * N_ / 8, 256>>>(shots, node, gcn_w);   // #2
    k_gcn<<<dim3(BW_ * 8, KQ_), 64>>>(shots);            // #3
    k_xfin<<<D_ / 64, 256>>>();                          // #4
    k_gates<<<dim3(8, KC_), 192, GATES_SMEM>>>(w_ih);    // #5
    k_greduce<<<BW_ * 4 * H_ / 256, 256>>>(b_ih, b_hh);  // #6
    k_lstm<<<dim3(4, B_), 256>>>();                      // #7
    k_out<<<D_ / 8, 256>>>(f1_w, f1_b);                  // #8
    k_s<<<B_ * N_ / 256, 256>>>(f2_w);                   // #9
    k_final<<<B_ * N_, 256>>>(res, f2_b);                // #10
}

// round 16
// speedup vs baseline: 1.8891x; 1.0011x over previous
#include <cuda_runtime.h>
#include <cstdint>

// Problem constants
static constexpr int B_   = 4;
static constexpr int W_   = 12;
static constexpr int N_   = 1024;
static constexpr int FIN_ = 32;
static constexpr int FOUT_= 32;
static constexpr int H_   = 256;
static constexpr int BW_  = B_ * W_;        // 48
static constexpr int D_   = N_ * FOUT_;     // 32768
static constexpr int KC_  = 128;            // split-K chunks for gates GEMM (k=256 each)
static constexpr int KQ_  = 4;              // split-K for gcn GEMM (k=256 each)

// ---------------- packed f32x2 helpers ----------------
#define FMA2(acc, a, b) asm("fma.rn.f32x2 %0, %1, %2, %0;" : "+l"(acc) : "l"(a), "l"(b))
#define PACK2(d, f)     asm("mov.b64 %0, {%1, %1};" : "=l"(d) : "f"(f))
#define UNPACK2(lo, hi, d) asm("mov.b64 {%0, %1}, %2;" : "=f"(lo), "=f"(hi) : "l"(d))

// ---------------- cp.async helpers ----------------
__device__ __forceinline__ void cp16(uint32_t dst, const void* src) {
    asm volatile("cp.async.cg.shared.global [%0], [%1], 16;" :: "r"(dst), "l"(src));
}
#define CP_COMMIT() asm volatile("cp.async.commit_group;")
#define CP_WAIT1()  asm volatile("cp.async.wait_group 1;")
#define CP_WAIT0()  asm volatile("cp.async.wait_group 0;")

// ---------------- scratch (static device globals; no allocation) ----------------
__device__ float g_deg[BW_ * N_];
__device__ float g_P[(size_t)BW_ * N_ * FOUT_];
__device__ float g_xpart[(size_t)KQ_ * BW_ * N_ * FOUT_];   // gcn split-K partials (25MB)
__device__ float g_XT[(size_t)D_ * BW_];                    // X transposed: [k][wb]
__device__ float g_part[(size_t)KC_ * BW_ * 4 * H_];        // gates split-K partials (25MB)
__device__ float g_gates[BW_ * 4 * H_];
__device__ float g_whhT[(size_t)H_ * 4 * H_];               // [k][j*4+r] interleaved
__device__ float g_hx[B_ * H_];                             // lstm h exchange
__device__ int   g_lcnt[B_];                                // lstm per-batch counters
__device__ float g_hn[B_ * H_];
__device__ float g_out[B_ * D_];
__device__ float g_s1[B_ * N_];
__device__ float g_s2[B_ * N_];

// ---------------- K0: transpose w_hh [4H][H] -> whhT [k][j*4+r]; reset counters --
// grid (32, 8), block (32, 8)
__global__ void k_whhT(const float* __restrict__ w_hh) {
    __shared__ float tile[32][33];
    int gb = blockIdx.x * 32;   // gate-row base (0..1023), never crosses 256 bnd
    int kb = blockIdx.y * 32;   // k base (0..255)
    int tx = threadIdx.x, ty = threadIdx.y;
    if (blockIdx.x == 0 && blockIdx.y == 0 && ty == 0 && tx < B_) g_lcnt[tx] = 0;
#pragma unroll
    for (int i = 0; i < 32; i += 8)
        tile[ty + i][tx] = w_hh[(size_t)(gb + ty + i) * H_ + kb + tx];
    __syncthreads();
    int r = gb >> 8;            // gate index (0..3), same for all tx
    int jb = gb & 255;          // unit base
#pragma unroll
    for (int i = 0; i < 32; i += 8)
        g_whhT[(size_t)(kb + ty + i) * (4 * H_) + (jb + tx) * 4 + r] = tile[tx][ty + i];
}

// ---------------- K1: fused degree + P -------------------------------------------
__global__ void k_degP(const float* __restrict__ shots, const float* __restrict__ node,
                       const float* __restrict__ gcn_w) {
    __shared__ float gw[FIN_ * FOUT_];
    int r0 = blockIdx.x * 8;
    int w  = (r0 / N_) % W_;            // rows bw-major: bw = b*W + w
    for (int i = threadIdx.x; i < FIN_ * FOUT_; i += 256)
        gw[i] = gcn_w[(size_t)w * FIN_ * FOUT_ + i];
    __syncthreads();
    int warp = threadIdx.x >> 5, lane = threadIdx.x & 31;
    int r = r0 + warp;
    const float4* p = (const float4*)(shots + (size_t)r * N_);
    float s = 0.f;
#pragma unroll
    for (int i = 0; i < 8; i++) {
        float4 v = p[lane + 32 * i];
        s += v.x + v.y + v.z + v.w;
    }
#pragma unroll
    for (int o = 16; o; o >>= 1) s += __shfl_xor_sync(0xffffffffu, s, o);
    float d = 1.0f / sqrtf(1.0f + s);
    if (lane == 0) g_deg[r] = d;

    float nv = node[(size_t)r * FIN_ + lane];
    float acc = 0.f;
#pragma unroll
    for (int f = 0; f < FIN_; f++) {
        float x = __shfl_sync(0xffffffffu, nv, f);
        acc += x * gw[f * FOUT_ + lane];
    }
    g_P[(size_t)r * FOUT_ + lane] = d * acc;
}

// ---------------- K3: xpart[kq] = shots[n, kq-chunk] @ P[kq-chunk, :] ----------
static constexpr int AS_ = 292;   // A_shT row stride (floats)
__global__ __launch_bounds__(64) void k_gcn(const float* __restrict__ shots) {
    __shared__ __align__(16) float AT[16 * AS_];   // [kk][f(row)]
    __shared__ __align__(16) float PS[16 * 32];    // [kk][col]
    int bw = blockIdx.x >> 3;
    int n0 = (blockIdx.x & 7) << 7;      // * 128
    int kq = blockIdx.y;
    int t = threadIdx.x;
    int tx = t & 3;
    int ty = t >> 2;
    const float* Abase = shots + (size_t)bw * N_ * N_;
    const float* Pbase = g_P + (size_t)bw * N_ * FOUT_;

    unsigned long long acc[4][8];
#pragma unroll
    for (int i = 0; i < 4; i++)
#pragma unroll
        for (int j = 0; j < 8; j++) acc[i][j] = 0ull;

    const int r8 = ty * 8;
    const int fr = r8 + ((r8 >> 5) << 2);

    for (int k0 = kq * 256; k0 < kq * 256 + 256; k0 += 16) {
#pragma unroll
        for (int i = 0; i < 8; i++) {
            int idx = t + 64 * i;
            int rr = idx >> 2, q = idx & 3;
            float4 v = *(const float4*)(Abase + (size_t)(n0 + rr) * N_ + k0 + 4 * q);
            int f = rr + ((rr >> 5) << 2);
            AT[(4 * q + 0) * AS_ + f] = v.x;
            AT[(4 * q + 1) * AS_ + f] = v.y;
            AT[(4 * q + 2) * AS_ + f] = v.z;
            AT[(4 * q + 3) * AS_ + f] = v.w;
        }
#pragma unroll
        for (int i = 0; i < 2; i++) {
            int idx = t + 64 * i;
            int kk = idx >> 3, c = idx & 7;
            *(float4*)&PS[kk * 32 + 4 * c] =
                *(const float4*)(Pbase + (size_t)(k0 + kk) * 32 + 4 * c);
        }
        __syncthreads();
#pragma unroll 4
        for (int kk = 0; kk < 16; kk++) {
            ulonglong2 aA = *(const ulonglong2*)&AT[kk * AS_ + fr];
            ulonglong2 aB = *(const ulonglong2*)&AT[kk * AS_ + fr + 4];
            float4 p0 = *(const float4*)&PS[kk * 32 + tx * 8];
            float4 p1 = *(const float4*)&PS[kk * 32 + tx * 8 + 4];
            unsigned long long ap[4];
            ap[0] = aA.x; ap[1] = aA.y; ap[2] = aB.x; ap[3] = aB.y;
            unsigned long long bb[8];
            PACK2(bb[0], p0.x); PACK2(bb[1], p0.y); PACK2(bb[2], p0.z); PACK2(bb[3], p0.w);
            PACK2(bb[4], p1.x); PACK2(bb[5], p1.y); PACK2(bb[6], p1.z); PACK2(bb[7], p1.w);
#pragma unroll
            for (int i = 0; i < 4; i++)
#pragma unroll
                for (int j = 0; j < 8; j++) FMA2(acc[i][j], ap[i], bb[j]);
        }
        __syncthreads();
    }

    float* Xp = g_xpart + (size_t)kq * BW_ * N_ * FOUT_ + (size_t)bw * N_ * FOUT_;
#pragma unroll
    for (int i = 0; i < 4; i++) {
        int ne = n0 + r8 + 2 * i;
        float lo[8], hi[8];
#pragma unroll
        for (int j = 0; j < 8; j++) UNPACK2(lo[j], hi[j], acc[i][j]);
        float4 o0 = {lo[0], lo[1], lo[2], lo[3]};
        float4 o1 = {lo[4], lo[5], lo[6], lo[7]};
        float4 o2 = {hi[0], hi[1], hi[2], hi[3]};
        float4 o3 = {hi[4], hi[5], hi[6], hi[7]};
        *(float4*)(Xp + (size_t)ne * 32 + tx * 8) = o0;
        *(float4*)(Xp + (size_t)ne * 32 + tx * 8 + 4) = o1;
        *(float4*)(Xp + (size_t)(ne + 1) * 32 + tx * 8) = o2;
        *(float4*)(Xp + (size_t)(ne + 1) * 32 + tx * 8 + 4) = o3;
    }
}

// ---------------- K3f: XT[k][wb] = d[n]*(sum_kq xpart + P), smem-tiled transpose -
// 512 blocks x 256 thr; block handles 64 consecutive k-rows.
__global__ void k_xfin(void) {
    __shared__ float tile[64 * 49];    // [rr][wb'] (stride 49: conflict-free)
    int rt = blockIdx.x * 64;
    int t = threadIdx.x;
#pragma unroll 4
    for (int pass = 0; pass < 12; pass++) {
        int p = pass * 256 + t;
        int bw = p >> 6, rr = p & 63;
        int r = rt + rr;
        float s = g_P[(size_t)bw * D_ + r];
#pragma unroll
        for (int kq = 0; kq < KQ_; kq++)
            s += g_xpart[(size_t)kq * BW_ * D_ + (size_t)bw * D_ + r];
        s *= g_deg[bw * N_ + (r >> 5)];
        int w = bw % W_, b = bw / W_;
        tile[rr * 49 + (w * B_ + b)] = s;
    }
    __syncthreads();
#pragma unroll 4
    for (int pass = 0; pass < 12; pass++) {
        int o = pass * 256 + t;
        int rr = o / 48, c = o % 48;
        g_XT[(size_t)(rt + rr) * BW_ + c] = tile[rr * 49 + c];
    }
}

// ---------------- K4: gates_x = X @ w_ih^T  (dual cp.async, deep split-K) -------
// Block = 48 wb x 128 g over K-chunk 256 (8 stages of 32 k). 192 threads.
// Grid (8, 128) = 1024 blocks -> all 4 smem-limited slots/SM stay full.
static constexpr int WROW_ = 36;                  // W smem row stride (floats)
static constexpr int WBUF_ = 128 * WROW_;         // 4608 floats per buffer
static constexpr int XS_   = 52;                  // XT smem row stride
static constexpr int XBUF_ = 32 * XS_;            // 1664 floats per buffer
static constexpr int GATES_SMEM = (2 * WBUF_ + 2 * XBUF_) * 4;   // 50176 B

__global__ __launch_bounds__(192, 4) void k_gates(const float* __restrict__ w_ih) {
    extern __shared__ __align__(16) float sm[];
    float* WS = sm;                 // [2][128][36]
    float* XT = sm + 2 * WBUF_;     // [2][32][52]
    const int g0 = blockIdx.x * 128;
    const int kc = blockIdx.y;
    const int kbase = kc * 256;
    const int t = threadIdx.x;
    const int warp = t >> 5, gl = t & 31;
    const int wb0 = warp * 8;
    const uint32_t ws_smem = (uint32_t)__cvta_generic_to_shared(WS);
    const uint32_t xt_smem = (uint32_t)__cvta_generic_to_shared(XT);

    unsigned long long acc[4][4];
#pragma unroll
    for (int i = 0; i < 4; i++)
#pragma unroll
        for (int j = 0; j < 4; j++) acc[i][j] = 0ull;

#define STAGE(bufi, k0)                                                            \
    do {                                                                           \
        for (int idx = t; idx < 1024; idx += 192) {                                \
            int g = idx >> 3, q = idx & 7;                                         \
            cp16(ws_smem + ((bufi) * WBUF_ + g * WROW_ + 4 * q) * 4,               \
                 w_ih + (size_t)(g0 + g) * D_ + (k0) + 4 * q);                     \
        }                                                                          \
        for (int idx = t; idx < 384; idx += 192) {                                 \
            int kk = idx / 12, q = idx % 12;                                       \
            cp16(xt_smem + ((bufi) * XBUF_ + kk * XS_ + 4 * q) * 4,                \
                 g_XT + (size_t)((k0) + kk) * BW_ + 4 * q);                        \
        }                                                                          \
        CP_COMMIT();                                                               \
    } while (0)

    STAGE(0, kbase);

    for (int s = 0; s < 8; s++) {
        int buf = s & 1;
        __syncthreads();   // previous compute done -> other buffer free
        if (s < 7) {
            STAGE(buf ^ 1, kbase + 32 * (s + 1));
            CP_WAIT1();
        } else {
            CP_WAIT0();
        }
        __syncthreads();
        const float* WB = WS + buf * WBUF_;
        const float* XB = XT + buf * XBUF_;
#pragma unroll
        for (int kkc = 0; kkc < 8; kkc++) {
            unsigned long long ap[4][4];
#pragma unroll
            for (int kk = 0; kk < 4; kk++) {
                int krow = kkc * 4 + kk;
                ulonglong2 xA = *(const ulonglong2*)&XB[krow * XS_ + wb0];
                ulonglong2 xB2 = *(const ulonglong2*)&XB[krow * XS_ + wb0 + 4];
                ap[kk][0] = xA.x; ap[kk][1] = xA.y; ap[kk][2] = xB2.x; ap[kk][3] = xB2.y;
            }
#pragma unroll
            for (int j = 0; j < 4; j++) {
                float4 v = *(const float4*)&WB[(gl + 32 * j) * WROW_ + kkc * 4];
                float wf[4] = {v.x, v.y, v.z, v.w};
#pragma unroll
                for (int kk = 0; kk < 4; kk++) {
                    unsigned long long b2;
                    PACK2(b2, wf[kk]);
#pragma unroll
                    for (int i = 0; i < 4; i++) FMA2(acc[i][j], ap[kk][i], b2);
                }
            }
        }
    }
#undef STAGE

    // epilogue -> split-K partials
#pragma unroll
    for (int i = 0; i < 4; i++) {
#pragma unroll
        for (int j = 0; j < 4; j++) {
            float lo, hi;
            UNPACK2(lo, hi, acc[i][j]);
            int gcol = g0 + gl + 32 * j;
            g_part[((size_t)kc * BW_ + wb0 + 2 * i) * 1024 + gcol] = lo;
            g_part[((size_t)kc * BW_ + wb0 + 2 * i + 1) * 1024 + gcol] = hi;
        }
    }
}

// ---------------- K4r: reduce split-K + biases ----------------------------------
__global__ void k_greduce(const float* __restrict__ b_ih, const float* __restrict__ b_hh) {
    int i = blockIdx.x * 256 + threadIdx.x;   // 0..49151
    int g = i & 1023;
    float s = b_ih[g] + b_hh[g];
#pragma unroll 8
    for (int kc = 0; kc < KC_; kc++) s += g_part[(size_t)kc * BW_ * 1024 + i];
    g_gates[i] = s;
}

// ---------------- K5: fused 12-step LSTM (16 blocks: 4 batches x 4 j-quarters) --
__global__ __launch_bounds__(256) void k_lstm() {
    __shared__ __align__(16) float hsh[H_];
    __shared__ float part[4][64][4];   // [kq][j_local][gate]
    int jq = blockIdx.x;
    int b  = blockIdx.y;
    int t = threadIdx.x;
    int wwarp = t >> 5, lane = t & 31;
    int kq = wwarp >> 1;                   // 0..3 (64 k each)
    int jl = (wwarp & 1) * 32 + lane;      // 0..63 local unit
    int jglob = jq * 64 + jl;
    const float4* wp = (const float4*)g_whhT + (size_t)(kq * 64) * H_ + jglob;
    float cc = 0.f;                        // finalizer state (t < 64)
    hsh[t] = 0.f;
    __syncthreads();

    for (int w = 0; w < W_; w++) {
        float a0 = 0.f, a1 = 0.f, a2 = 0.f, a3 = 0.f;
        float4 bufA[8], bufB[8];
#pragma unroll
        for (int u = 0; u < 8; u++) bufA[u] = wp[(size_t)u * H_];
#pragma unroll
        for (int kb = 0; kb < 64; kb += 16) {
#pragma unroll
            for (int u = 0; u < 8; u++)
                bufB[u] = wp[(size_t)((kb + 8 + u) & 63) * H_];
#pragma unroll
            for (int u = 0; u < 8; u++) {
                float hk = hsh[kq * 64 + kb + u];
                a0 += bufA[u].x * hk;
                a1 += bufA[u].y * hk;
                a2 += bufA[u].z * hk;
                a3 += bufA[u].w * hk;
            }
#pragma unroll
            for (int u = 0; u < 8; u++)
                bufA[u] = wp[(size_t)((kb + 16 + u) & 63) * H_];
#pragma unroll
            for (int u = 0; u < 8; u++) {
                float hk = hsh[kq * 64 + kb + 8 + u];
                a0 += bufB[u].x * hk;
                a1 += bufB[u].y * hk;
                a2 += bufB[u].z * hk;
                a3 += bufB[u].w * hk;
            }
        }
        part[kq][jl][0] = a0;
        part[kq][jl][1] = a1;
        part[kq][jl][2] = a2;
        part[kq][jl][3] = a3;
        __syncthreads();

        if (t < 64) {
            int j = jq * 64 + t;
            const float* gx = g_gates + ((size_t)(w * B_ + b)) * 4 * H_;
            float s0 = gx[j]           + part[0][t][0] + part[1][t][0] + part[2][t][0] + part[3][t][0];
            float s1 = gx[H_ + j]      + part[0][t][1] + part[1][t][1] + part[2][t][1] + part[3][t][1];
            float s2 = gx[2 * H_ + j]  + part[0][t][2] + part[1][t][2] + part[2][t][2] + part[3][t][2];
            float s3 = gx[3 * H_ + j]  + part[0][t][3] + part[1][t][3] + part[2][t][3] + part[3][t][3];
            float ig = 1.0f / (1.0f + expf(-s0));
            float fg = 1.0f / (1.0f + expf(-s1));
            float gg = tanhf(s2);
            float og = 1.0f / (1.0f + expf(-s3));
            cc = fg * cc + ig * gg;
            float hv = og * tanhf(cc);
            asm volatile("st.global.cg.f32 [%0], %1;" :: "l"(&g_hx[b * H_ + j]), "f"(hv));
        }
        __syncthreads();

        if (t == 0) {
            int target = 4 * (w + 1);
            asm volatile("red.release.gpu.global.add.s32 [%0], 1;" :: "l"(&g_lcnt[b]));
            int v;
            do {
                asm volatile("ld.acquire.gpu.global.s32 %0, [%1];" : "=r"(v) : "l"(&g_lcnt[b]));
            } while (v < target);
        }
        __syncthreads();

        float hv;
        asm volatile("ld.global.cg.f32 %0, [%1];" : "=f"(hv) : "l"(&g_hx[b * H_ + t]));
        hsh[t] = hv;
        __syncthreads();
    }
    if (jq == 0) g_hn[b * H_ + t] = hsh[t];
}

// ---------------- K6: out[b, r] = hn[b,:]·f1_w[r,:] + f1_b[r] -------------------
__global__ void k_out(const float* __restrict__ f1_w, const float* __restrict__ f1_b) {
    __shared__ __align__(16) float hsh[B_ * H_];
    for (int i = threadIdx.x; i < B_ * H_; i += 256) hsh[i] = g_hn[i];
    __syncthreads();
    int warp = threadIdx.x >> 5, lane = threadIdx.x & 31;
    int r = blockIdx.x * 8 + warp;
    const float4* Wr = (const float4*)(f1_w + (size_t)r * H_);
    float a[B_] = {0.f, 0.f, 0.f, 0.f};
#pragma unroll
    for (int t = 0; t < 2; t++) {
        int idx = lane + 32 * t;
        float4 wv = Wr[idx];
#pragma unroll
        for (int b = 0; b < B_; b++) {
            float4 hv = *(const float4*)&hsh[b * H_ + idx * 4];
            a[b] += wv.x * hv.x + wv.y * hv.y + wv.z * hv.z + wv.w * hv.w;
        }
    }
#pragma unroll
    for (int b = 0; b < B_; b++) {
#pragma unroll
        for (int o = 16; o; o >>= 1) a[b] += __shfl_xor_sync(0xffffffffu, a[b], o);
    }
    if (lane == 0) {
        float bb = f1_b[r];
#pragma unroll
        for (int b = 0; b < B_; b++) g_out[(size_t)b * D_ + r] = a[b] + bb;
    }
}

// ---------------- K6c: s1[b,n], s2[b,n] -----------------------------------------
__global__ void k_s(const float* __restrict__ f2_w) {
    int idx = blockIdx.x * 256 + threadIdx.x;
    const float4* v4 = (const float4*)(g_out + (size_t)idx * FOUT_);
    const float4* w1 = (const float4*)(f2_w);
    const float4* w2 = (const float4*)(f2_w + FOUT_);
    float s1 = 0.f, s2 = 0.f;
#pragma unroll
    for (int t = 0; t < 8; t++) {
        float4 v = v4[t], a = w1[t], b = w2[t];
        s1 += v.x * a.x + v.y * a.y + v.z * a.z + v.w * a.w;
        s2 += v.x * b.x + v.y * b.y + v.z * b.z + v.w * b.w;
    }
    g_s1[idx] = s1;
    g_s2[idx] = s2;
}

// ---------------- K7: scores, keep mask, L1 row-normalize, write output ----------
__global__ void k_final(float* __restrict__ res, const float* __restrict__ f2_b) {
    __shared__ float s1s[N_], s2s[N_];
    __shared__ float wsum[8];
    __shared__ float total;
    int b = blockIdx.x >> 10;
    int i = blockIdx.x & 1023;
    for (int t = threadIdx.x; t < N_; t += 256) {
        s1s[t] = g_s1[b * N_ + t];
        s2s[t] = g_s2[b * N_ + t];
    }
    __syncthreads();
    float bias = f2_b[0];
    float s1i = s1s[i], s2i = s2s[i];
    float v[4];
    float asum = 0.f;
#pragma unroll
    for (int t = 0; t < 4; t++) {
        int j = threadIdx.x + t * 256;
        float sc = s1i + s2s[j] + bias;
        float st = s1s[j] + s2i + bias;
        float val;
        if (i == j) {
            val = sc;
        } else {
            bool keep = (i < j) ? (sc >= st && sc > 0.f) : (sc > st && sc >= 0.f);
            val = keep ? sc : 0.f;
        }
        v[t] = val;
        asum += fabsf(val);
    }
    int warp = threadIdx.x >> 5, lane = threadIdx.x & 31;
#pragma unroll
    for (int o = 16; o; o >>= 1) asum += __shfl_xor_sync(0xffffffffu, asum, o);
    if (lane == 0) wsum[warp] = asum;
    __syncthreads();
    if (threadIdx.x == 0) {
        float s = 0.f;
#pragma unroll
        for (int k = 0; k < 8; k++) s += wsum[k];
        total = s;
    }
    __syncthreads();
    float inv = 1.0f / fmaxf(total, 1e-12f);
    float* row = res + ((size_t)b * N_ + i) * N_;
#pragma unroll
    for (int t = 0; t < 4; t++) row[threadIdx.x + t * 256] = v[t] * inv;
}

// =================================================================================
extern "C" void kernel_launch(void* const* d_in, const int* in_sizes, int n_in,
                              void* d_out, int out_size) {
    const float* shots = (const float*)d_in[0];
    const float* node  = (const float*)d_in[1];
    // d_in[2] = 'a' (unused by reference)
    const float* gcn_w = (const float*)d_in[3];
    const float* w_ih  = (const float*)d_in[4];
    const float* w_hh  = (const float*)d_in[5];
    const float* b_ih  = (const float*)d_in[6];
    const float* b_hh  = (const float*)d_in[7];
    const float* f1_w  = (const float*)d_in[8];
    const float* f1_b  = (const float*)d_in[9];
    const float* f2_w  = (const float*)d_in[10];
    const float* f2_b  = (const float*)d_in[11];
    float* res = (float*)d_out;

    cudaFuncSetAttribute(k_gates, cudaFuncAttributeMaxDynamicSharedMemorySize, GATES_SMEM);

    k_whhT<<<dim3(32, 8), dim3(32, 8)>>>(w_hh);          // #1 (also resets g_lcnt)
    k_degP<<<BW_ * N_ / 8, 256>>>(shots, node, gcn_w);   // #2
    k_gcn<<<dim3(BW_ * 8, KQ_), 64>>>(shots);            // #3
    k_xfin<<<D_ / 64, 256>>>();                          // #4
    k_gates<<<dim3(8, KC_), 192, GATES_SMEM>>>(w_ih);    // #5
    k_greduce<<<BW_ * 4 * H_ / 256, 256>>>(b_ih, b_hh);  // #6
    k_lstm<<<dim3(4, B_), 256>>>();                      // #7
    k_out<<<D_ / 8, 256>>>(f1_w, f1_b);                  // #8
    k_s<<<B_ * N_ / 256, 256>>>(f2_w);                   // #9
    k_final<<<B_ * N_, 256>>>(res, f2_b);                // #10
}

// round 17
// speedup vs baseline: 2.2549x; 1.1936x over previous
#include <cuda_runtime.h>
#include <cstdint>

// Problem constants
static constexpr int B_   = 4;
static constexpr int W_   = 12;
static constexpr int N_   = 1024;
static constexpr int FIN_ = 32;
static constexpr int FOUT_= 32;
static constexpr int H_   = 256;
static constexpr int BW_  = B_ * W_;        // 48
static constexpr int D_   = N_ * FOUT_;     // 32768
static constexpr int KC_  = 128;            // split-K chunks for gates GEMM (k=256 each)
static constexpr int KQ_  = 4;              // split-K for gcn GEMM (k=256 each)

// ---------------- packed f32x2 helpers ----------------
#define FMA2(acc, a, b) asm("fma.rn.f32x2 %0, %1, %2, %0;" : "+l"(acc) : "l"(a), "l"(b))
#define PACK2(d, f)     asm("mov.b64 %0, {%1, %1};" : "=l"(d) : "f"(f))
#define UNPACK2(lo, hi, d) asm("mov.b64 {%0, %1}, %2;" : "=f"(lo), "=f"(hi) : "l"(d))

// ---------------- cp.async helpers ----------------
__device__ __forceinline__ void cp16(uint32_t dst, const void* src) {
    asm volatile("cp.async.cg.shared.global [%0], [%1], 16;" :: "r"(dst), "l"(src));
}
#define CP_COMMIT() asm volatile("cp.async.commit_group;")
#define CP_WAIT1()  asm volatile("cp.async.wait_group 1;")
#define CP_WAIT0()  asm volatile("cp.async.wait_group 0;")

// ---------------- scratch (static device globals; no allocation) ----------------
__device__ float g_deg[BW_ * N_];
__device__ float g_P[(size_t)BW_ * N_ * FOUT_];
__device__ float g_xpart[(size_t)KQ_ * BW_ * N_ * FOUT_];   // gcn split-K partials
__device__ float g_XT[(size_t)D_ * BW_];                    // X transposed: [k][wb]
__device__ float g_part[(size_t)KC_ * BW_ * 4 * H_];        // gates split-K partials
__device__ float g_gates[BW_ * 4 * H_];
__device__ float g_whhT[(size_t)H_ * 4 * H_];               // [k][j*4+r] interleaved
__device__ float g_hx[B_ * H_];                             // lstm h exchange
__device__ int   g_lcnt[B_];                                // lstm per-batch counters
__device__ float g_hn[B_ * H_];
__device__ float g_out[B_ * D_];
__device__ float g_s1[B_ * N_];
__device__ float g_s2[B_ * N_];

// ---------------- K0: transpose w_hh [4H][H] -> whhT [k][j*4+r]; reset counters --
// grid (32, 8), block (32, 8)
__global__ void k_whhT(const float* __restrict__ w_hh) {
    __shared__ float tile[32][33];
    int gb = blockIdx.x * 32;   // gate-row base (0..1023), never crosses 256 bnd
    int kb = blockIdx.y * 32;   // k base (0..255)
    int tx = threadIdx.x, ty = threadIdx.y;
    if (blockIdx.x == 0 && blockIdx.y == 0 && ty == 0 && tx < B_) g_lcnt[tx] = 0;
#pragma unroll
    for (int i = 0; i < 32; i += 8)
        tile[ty + i][tx] = w_hh[(size_t)(gb + ty + i) * H_ + kb + tx];
    __syncthreads();
    int r = gb >> 8;            // gate index (0..3), same for all tx
    int jb = gb & 255;          // unit base
#pragma unroll
    for (int i = 0; i < 32; i += 8)
        g_whhT[(size_t)(kb + ty + i) * (4 * H_) + (jb + tx) * 4 + r] = tile[tx][ty + i];
}

// ---------------- K1: fused degree + P -------------------------------------------
__global__ void k_degP(const float* __restrict__ shots, const float* __restrict__ node,
                       const float* __restrict__ gcn_w) {
    __shared__ float gw[FIN_ * FOUT_];
    int r0 = blockIdx.x * 8;
    int w  = (r0 / N_) % W_;            // rows bw-major: bw = b*W + w
    for (int i = threadIdx.x; i < FIN_ * FOUT_; i += 256)
        gw[i] = gcn_w[(size_t)w * FIN_ * FOUT_ + i];
    __syncthreads();
    int warp = threadIdx.x >> 5, lane = threadIdx.x & 31;
    int r = r0 + warp;
    const float4* p = (const float4*)(shots + (size_t)r * N_);
    float s = 0.f;
#pragma unroll
    for (int i = 0; i < 8; i++) {
        float4 v = p[lane + 32 * i];
        s += v.x + v.y + v.z + v.w;
    }
#pragma unroll
    for (int o = 16; o; o >>= 1) s += __shfl_xor_sync(0xffffffffu, s, o);
    float d = 1.0f / sqrtf(1.0f + s);
    if (lane == 0) g_deg[r] = d;

    float nv = node[(size_t)r * FIN_ + lane];
    float acc = 0.f;
#pragma unroll
    for (int f = 0; f < FIN_; f++) {
        float x = __shfl_sync(0xffffffffu, nv, f);
        acc += x * gw[f * FOUT_ + lane];
    }
    g_P[(size_t)r * FOUT_ + lane] = d * acc;
}

// ---------------- K3: xpart[kq] = shots[n, kq-chunk] @ P[kq-chunk, :] ----------
static constexpr int AS_ = 292;   // A_shT row stride (floats)
__global__ __launch_bounds__(64) void k_gcn(const float* __restrict__ shots) {
    __shared__ __align__(16) float AT[16 * AS_];   // [kk][f(row)]
    __shared__ __align__(16) float PS[16 * 32];    // [kk][col]
    int bw = blockIdx.x >> 3;
    int n0 = (blockIdx.x & 7) << 7;      // * 128
    int kq = blockIdx.y;
    int t = threadIdx.x;
    int tx = t & 3;
    int ty = t >> 2;
    const float* Abase = shots + (size_t)bw * N_ * N_;
    const float* Pbase = g_P + (size_t)bw * N_ * FOUT_;

    unsigned long long acc[4][8];
#pragma unroll
    for (int i = 0; i < 4; i++)
#pragma unroll
        for (int j = 0; j < 8; j++) acc[i][j] = 0ull;

    const int r8 = ty * 8;
    const int fr = r8 + ((r8 >> 5) << 2);

    for (int k0 = kq * 256; k0 < kq * 256 + 256; k0 += 16) {
#pragma unroll
        for (int i = 0; i < 8; i++) {
            int idx = t + 64 * i;
            int rr = idx >> 2, q = idx & 3;
            float4 v = *(const float4*)(Abase + (size_t)(n0 + rr) * N_ + k0 + 4 * q);
            int f = rr + ((rr >> 5) << 2);
            AT[(4 * q + 0) * AS_ + f] = v.x;
            AT[(4 * q + 1) * AS_ + f] = v.y;
            AT[(4 * q + 2) * AS_ + f] = v.z;
            AT[(4 * q + 3) * AS_ + f] = v.w;
        }
#pragma unroll
        for (int i = 0; i < 2; i++) {
            int idx = t + 64 * i;
            int kk = idx >> 3, c = idx & 7;
            *(float4*)&PS[kk * 32 + 4 * c] =
                *(const float4*)(Pbase + (size_t)(k0 + kk) * 32 + 4 * c);
        }
        __syncthreads();
#pragma unroll 4
        for (int kk = 0; kk < 16; kk++) {
            ulonglong2 aA = *(const ulonglong2*)&AT[kk * AS_ + fr];
            ulonglong2 aB = *(const ulonglong2*)&AT[kk * AS_ + fr + 4];
            float4 p0 = *(const float4*)&PS[kk * 32 + tx * 8];
            float4 p1 = *(const float4*)&PS[kk * 32 + tx * 8 + 4];
            unsigned long long ap[4];
            ap[0] = aA.x; ap[1] = aA.y; ap[2] = aB.x; ap[3] = aB.y;
            unsigned long long bb[8];
            PACK2(bb[0], p0.x); PACK2(bb[1], p0.y); PACK2(bb[2], p0.z); PACK2(bb[3], p0.w);
            PACK2(bb[4], p1.x); PACK2(bb[5], p1.y); PACK2(bb[6], p1.z); PACK2(bb[7], p1.w);
#pragma unroll
            for (int i = 0; i < 4; i++)
#pragma unroll
                for (int j = 0; j < 8; j++) FMA2(acc[i][j], ap[i], bb[j]);
        }
        __syncthreads();
    }

    float* Xp = g_xpart + (size_t)kq * BW_ * N_ * FOUT_ + (size_t)bw * N_ * FOUT_;
#pragma unroll
    for (int i = 0; i < 4; i++) {
        int ne = n0 + r8 + 2 * i;
        float lo[8], hi[8];
#pragma unroll
        for (int j = 0; j < 8; j++) UNPACK2(lo[j], hi[j], acc[i][j]);
        float4 o0 = {lo[0], lo[1], lo[2], lo[3]};
        float4 o1 = {lo[4], lo[5], lo[6], lo[7]};
        float4 o2 = {hi[0], hi[1], hi[2], hi[3]};
        float4 o3 = {hi[4], hi[5], hi[6], hi[7]};
        *(float4*)(Xp + (size_t)ne * 32 + tx * 8) = o0;
        *(float4*)(Xp + (size_t)ne * 32 + tx * 8 + 4) = o1;
        *(float4*)(Xp + (size_t)(ne + 1) * 32 + tx * 8) = o2;
        *(float4*)(Xp + (size_t)(ne + 1) * 32 + tx * 8 + 4) = o3;
    }
}

// ---------------- K3f: XT[k][wb] = d[n]*(sum_kq xpart + P), smem-tiled transpose -
// 512 blocks x 256 thr; block handles 64 consecutive k-rows.
__global__ void k_xfin(void) {
    __shared__ float tile[64 * 49];    // [rr][wb'] (stride 49: conflict-free)
    int rt = blockIdx.x * 64;
    int t = threadIdx.x;
#pragma unroll 4
    for (int pass = 0; pass < 12; pass++) {
        int p = pass * 256 + t;
        int bw = p >> 6, rr = p & 63;
        int r = rt + rr;
        float s = g_P[(size_t)bw * D_ + r];
#pragma unroll
        for (int kq = 0; kq < KQ_; kq++)
            s += g_xpart[(size_t)kq * BW_ * D_ + (size_t)bw * D_ + r];
        s *= g_deg[bw * N_ + (r >> 5)];
        int w = bw % W_, b = bw / W_;
        tile[rr * 49 + (w * B_ + b)] = s;
    }
    __syncthreads();
#pragma unroll 4
    for (int pass = 0; pass < 12; pass++) {
        int o = pass * 256 + t;
        int rr = o / 48, c = o % 48;
        g_XT[(size_t)(rt + rr) * BW_ + c] = tile[rr * 49 + c];
    }
}

// ---------------- K4: gates_x = X @ w_ih^T  (dual cp.async, deep split-K) -------
static constexpr int WROW_ = 36;                  // W smem row stride (floats)
static constexpr int WBUF_ = 128 * WROW_;         // 4608 floats per buffer
static constexpr int XS_   = 52;                  // XT smem row stride
static constexpr int XBUF_ = 32 * XS_;            // 1664 floats per buffer
static constexpr int GATES_SMEM = (2 * WBUF_ + 2 * XBUF_) * 4;   // 50176 B

__global__ __launch_bounds__(192, 4) void k_gates(const float* __restrict__ w_ih) {
    extern __shared__ __align__(16) float sm[];
    float* WS = sm;                 // [2][128][36]
    float* XT = sm + 2 * WBUF_;     // [2][32][52]
    const int g0 = blockIdx.x * 128;
    const int kc = blockIdx.y;
    const int kbase = kc * 256;
    const int t = threadIdx.x;
    const int warp = t >> 5, gl = t & 31;
    const int wb0 = warp * 8;
    const uint32_t ws_smem = (uint32_t)__cvta_generic_to_shared(WS);
    const uint32_t xt_smem = (uint32_t)__cvta_generic_to_shared(XT);

    unsigned long long acc[4][4];
#pragma unroll
    for (int i = 0; i < 4; i++)
#pragma unroll
        for (int j = 0; j < 4; j++) acc[i][j] = 0ull;

#define STAGE(bufi, k0)                                                            \
    do {                                                                           \
        for (int idx = t; idx < 1024; idx += 192) {                                \
            int g = idx >> 3, q = idx & 7;                                         \
            cp16(ws_smem + ((bufi) * WBUF_ + g * WROW_ + 4 * q) * 4,               \
                 w_ih + (size_t)(g0 + g) * D_ + (k0) + 4 * q);                     \
        }                                                                          \
        for (int idx = t; idx < 384; idx += 192) {                                 \
            int kk = idx / 12, q = idx % 12;                                       \
            cp16(xt_smem + ((bufi) * XBUF_ + kk * XS_ + 4 * q) * 4,                \
                 g_XT + (size_t)((k0) + kk) * BW_ + 4 * q);                        \
        }                                                                          \
        CP_COMMIT();                                                               \
    } while (0)

    STAGE(0, kbase);

    for (int s = 0; s < 8; s++) {
        int buf = s & 1;
        __syncthreads();   // previous compute done -> other buffer free
        if (s < 7) {
            STAGE(buf ^ 1, kbase + 32 * (s + 1));
            CP_WAIT1();
        } else {
            CP_WAIT0();
        }
        __syncthreads();
        const float* WB = WS + buf * WBUF_;
        const float* XB = XT + buf * XBUF_;
#pragma unroll
        for (int kkc = 0; kkc < 8; kkc++) {
            unsigned long long ap[4][4];
#pragma unroll
            for (int kk = 0; kk < 4; kk++) {
                int krow = kkc * 4 + kk;
                ulonglong2 xA = *(const ulonglong2*)&XB[krow * XS_ + wb0];
                ulonglong2 xB2 = *(const ulonglong2*)&XB[krow * XS_ + wb0 + 4];
                ap[kk][0] = xA.x; ap[kk][1] = xA.y; ap[kk][2] = xB2.x; ap[kk][3] = xB2.y;
            }
#pragma unroll
            for (int j = 0; j < 4; j++) {
                float4 v = *(const float4*)&WB[(gl + 32 * j) * WROW_ + kkc * 4];
                float wf[4] = {v.x, v.y, v.z, v.w};
#pragma unroll
                for (int kk = 0; kk < 4; kk++) {
                    unsigned long long b2;
                    PACK2(b2, wf[kk]);
#pragma unroll
                    for (int i = 0; i < 4; i++) FMA2(acc[i][j], ap[kk][i], b2);
                }
            }
        }
    }
#undef STAGE

    // epilogue -> split-K partials
#pragma unroll
    for (int i = 0; i < 4; i++) {
#pragma unroll
        for (int j = 0; j < 4; j++) {
            float lo, hi;
            UNPACK2(lo, hi, acc[i][j]);
            int gcol = g0 + gl + 32 * j;
            g_part[((size_t)kc * BW_ + wb0 + 2 * i) * 1024 + gcol] = lo;
            g_part[((size_t)kc * BW_ + wb0 + 2 * i + 1) * 1024 + gcol] = hi;
        }
    }
}

// ---------------- K4r: reduce split-K + biases ----------------------------------
__global__ void k_greduce(const float* __restrict__ b_ih, const float* __restrict__ b_hh) {
    int i = blockIdx.x * 256 + threadIdx.x;   // 0..49151
    int g = i & 1023;
    float s = b_ih[g] + b_hh[g];
#pragma unroll 8
    for (int kc = 0; kc < KC_; kc++) s += g_part[(size_t)kc * BW_ * 1024 + i];
    g_gates[i] = s;
}

// ---------------- K5: fused 12-step LSTM (32 blocks, weights in REGISTERS) ------
// Grid (8 jq, 4 b). Block: 256 threads; warp = k-chunk (32 k), lane = local unit
// (32 j/block). Each thread holds its 32 float4 gate weights in registers for
// ALL 12 steps (loaded once, coalesced). Per-step: 32 broadcast LDS + 128 FMA.
// k-chunk partials reduced in smem; h exchanged via st.cg + release/acquire.
__global__ __launch_bounds__(256) void k_lstm() {
    __shared__ __align__(16) float hsh[H_];
    __shared__ float part[8][32][4];   // [kq][j_local][gate]
    int jq = blockIdx.x;               // 0..7
    int b  = blockIdx.y;
    int t = threadIdx.x;
    int kq = t >> 5, lane = t & 31;    // warp = k-chunk, lane = local j
    int jglob = jq * 32 + lane;
    float cc = 0.f;                    // finalizer state (t < 32)
    hsh[t] = 0.f;

    // load weights once: 32 float4 per thread, coalesced across lanes
    const float4* wp = (const float4*)g_whhT + (size_t)(kq * 32) * H_ + jglob;
    float4 wreg[32];
#pragma unroll
    for (int u = 0; u < 32; u++) wreg[u] = wp[(size_t)u * H_];
    __syncthreads();

    for (int w = 0; w < W_; w++) {
        float a0 = 0.f, a1 = 0.f, a2 = 0.f, a3 = 0.f;
#pragma unroll
        for (int u = 0; u < 32; u++) {
            float hk = hsh[kq * 32 + u];
            a0 += wreg[u].x * hk;
            a1 += wreg[u].y * hk;
            a2 += wreg[u].z * hk;
            a3 += wreg[u].w * hk;
        }
        part[kq][lane][0] = a0;
        part[kq][lane][1] = a1;
        part[kq][lane][2] = a2;
        part[kq][lane][3] = a3;
        __syncthreads();

        if (t < 32) {
            int j = jq * 32 + t;
            const float* gx = g_gates + ((size_t)(w * B_ + b)) * 4 * H_;
            float s0 = gx[j],          s1 = gx[H_ + j];
            float s2 = gx[2 * H_ + j], s3 = gx[3 * H_ + j];
#pragma unroll
            for (int q = 0; q < 8; q++) {
                s0 += part[q][t][0];
                s1 += part[q][t][1];
                s2 += part[q][t][2];
                s3 += part[q][t][3];
            }
            float ig = 1.0f / (1.0f + expf(-s0));
            float fg = 1.0f / (1.0f + expf(-s1));
            float gg = tanhf(s2);
            float og = 1.0f / (1.0f + expf(-s3));
            cc = fg * cc + ig * gg;
            float hv = og * tanhf(cc);
            asm volatile("st.global.cg.f32 [%0], %1;" :: "l"(&g_hx[b * H_ + j]), "f"(hv));
        }
        __syncthreads();   // finalizer stores issued before the count

        if (t == 0) {
            int target = 8 * (w + 1);
            asm volatile("red.release.gpu.global.add.s32 [%0], 1;" :: "l"(&g_lcnt[b]));
            int v;
            do {
                asm volatile("ld.acquire.gpu.global.s32 %0, [%1];" : "=r"(v) : "l"(&g_lcnt[b]));
            } while (v < target);
        }
        __syncthreads();

        float hv;
        asm volatile("ld.global.cg.f32 %0, [%1];" : "=f"(hv) : "l"(&g_hx[b * H_ + t]));
        hsh[t] = hv;
        __syncthreads();
    }
    if (jq == 0) g_hn[b * H_ + t] = hsh[t];
}

// ---------------- K6: out[b, r] = hn[b,:]·f1_w[r,:] + f1_b[r] -------------------
__global__ void k_out(const float* __restrict__ f1_w, const float* __restrict__ f1_b) {
    __shared__ __align__(16) float hsh[B_ * H_];
    for (int i = threadIdx.x; i < B_ * H_; i += 256) hsh[i] = g_hn[i];
    __syncthreads();
    int warp = threadIdx.x >> 5, lane = threadIdx.x & 31;
    int r = blockIdx.x * 8 + warp;
    const float4* Wr = (const float4*)(f1_w + (size_t)r * H_);
    float a[B_] = {0.f, 0.f, 0.f, 0.f};
#pragma unroll
    for (int t = 0; t < 2; t++) {
        int idx = lane + 32 * t;
        float4 wv = Wr[idx];
#pragma unroll
        for (int b = 0; b < B_; b++) {
            float4 hv = *(const float4*)&hsh[b * H_ + idx * 4];
            a[b] += wv.x * hv.x + wv.y * hv.y + wv.z * hv.z + wv.w * hv.w;
        }
    }
#pragma unroll
    for (int b = 0; b < B_; b++) {
#pragma unroll
        for (int o = 16; o; o >>= 1) a[b] += __shfl_xor_sync(0xffffffffu, a[b], o);
    }
    if (lane == 0) {
        float bb = f1_b[r];
#pragma unroll
        for (int b = 0; b < B_; b++) g_out[(size_t)b * D_ + r] = a[b] + bb;
    }
}

// ---------------- K6c: s1[b,n], s2[b,n] -----------------------------------------
__global__ void k_s(const float* __restrict__ f2_w) {
    int idx = blockIdx.x * 256 + threadIdx.x;
    const float4* v4 = (const float4*)(g_out + (size_t)idx * FOUT_);
    const float4* w1 = (const float4*)(f2_w);
    const float4* w2 = (const float4*)(f2_w + FOUT_);
    float s1 = 0.f, s2 = 0.f;
#pragma unroll
    for (int t = 0; t < 8; t++) {
        float4 v = v4[t], a = w1[t], b = w2[t];
        s1 += v.x * a.x + v.y * a.y + v.z * a.z + v.w * a.w;
        s2 += v.x * b.x + v.y * b.y + v.z * b.z + v.w * b.w;
    }
    g_s1[idx] = s1;
    g_s2[idx] = s2;
}

// ---------------- K7: scores, keep mask, L1 row-normalize, write output ----------
__global__ void k_final(float* __restrict__ res, const float* __restrict__ f2_b) {
    __shared__ float s1s[N_], s2s[N_];
    __shared__ float wsum[8];
    __shared__ float total;
    int b = blockIdx.x >> 10;
    int i = blockIdx.x & 1023;
    for (int t = threadIdx.x; t < N_; t += 256) {
        s1s[t] = g_s1[b * N_ + t];
        s2s[t] = g_s2[b * N_ + t];
    }
    __syncthreads();
    float bias = f2_b[0];
    float s1i = s1s[i], s2i = s2s[i];
    float v[4];
    float asum = 0.f;
#pragma unroll
    for (int t = 0; t < 4; t++) {
        int j = threadIdx.x + t * 256;
        float sc = s1i + s2s[j] + bias;
        float st = s1s[j] + s2i + bias;
        float val;
        if (i == j) {
            val = sc;
        } else {
            bool keep = (i < j) ? (sc >= st && sc > 0.f) : (sc > st && sc >= 0.f);
            val = keep ? sc : 0.f;
        }
        v[t] = val;
        asum += fabsf(val);
    }
    int warp = threadIdx.x >> 5, lane = threadIdx.x & 31;
#pragma unroll
    for (int o = 16; o; o >>= 1) asum += __shfl_xor_sync(0xffffffffu, asum, o);
    if (lane == 0) wsum[warp] = asum;
    __syncthreads();
    if (threadIdx.x == 0) {
        float s = 0.f;
#pragma unroll
        for (int k = 0; k < 8; k++) s += wsum[k];
        total = s;
    }
    __syncthreads();
    float inv = 1.0f / fmaxf(total, 1e-12f);
    float* row = res + ((size_t)b * N_ + i) * N_;
#pragma unroll
    for (int t = 0; t < 4; t++) row[threadIdx.x + t * 256] = v[t] * inv;
}

// =================================================================================
extern "C" void kernel_launch(void* const* d_in, const int* in_sizes, int n_in,
                              void* d_out, int out_size) {
    const float* shots = (const float*)d_in[0];
    const float* node  = (const float*)d_in[1];
    // d_in[2] = 'a' (unused by reference)
    const float* gcn_w = (const float*)d_in[3];
    const float* w_ih  = (const float*)d_in[4];
    const float* w_hh  = (const float*)d_in[5];
    const float* b_ih  = (const float*)d_in[6];
    const float* b_hh  = (const float*)d_in[7];
    const float* f1_w  = (const float*)d_in[8];
    const float* f1_b  = (const float*)d_in[9];
    const float* f2_w  = (const float*)d_in[10];
    const float* f2_b  = (const float*)d_in[11];
    float* res = (float*)d_out;

    cudaFuncSetAttribute(k_gates, cudaFuncAttributeMaxDynamicSharedMemorySize, GATES_SMEM);

    k_degP<<<BW_ * N_ / 8, 256>>>(shots, node, gcn_w);   // #1
    k_gcn<<<dim3(BW_ * 8, KQ_), 64>>>(shots);            // #2
    k_xfin<<<D_ / 64, 256>>>();                          // #3
    k_gates<<<dim3(8, KC_), 192, GATES_SMEM>>>(w_ih);    // #4  <- ncu sample slot
    k_whhT<<<dim3(32, 8), dim3(32, 8)>>>(w_hh);          // #5 (also resets g_lcnt)
    k_greduce<<<BW_ * 4 * H_ / 256, 256>>>(b_ih, b_hh);  // #6
    k_lstm<<<dim3(8, B_), 256>>>();                      // #7
    k_out<<<D_ / 8, 256>>>(f1_w, f1_b);                  // #8
    k_s<<<B_ * N_ / 256, 256>>>(f2_w);                   // #9
    k_final<<<B_ * N_, 256>>>(res, f2_b);                // #10
}